// round 2
// baseline (speedup 1.0000x reference)
#include <cuda_runtime.h>
#include <math.h>

#define B_ROWS 131072
#define NEXP   4

// ---------------- device scratch (no dynamic allocation allowed) ----------
__device__ int    g_count[NEXP];
__device__ double g_probsum[NEXP];
__device__ float  g_avg[NEXP];
__device__ int    g_bucket[NEXP * B_ROWS];

// ---------------- reset ---------------------------------------------------
__global__ void k_reset() {
  int t = threadIdx.x;
  if (t < NEXP) { g_count[t] = 0; g_probsum[t] = 0.0; }
}

// ---------------- gate: softmax-top1 + bucket compaction -------------------
// 8 warps/block, one row per warp.
__global__ void __launch_bounds__(256) k_gate(
    const float* __restrict__ zg, const float* __restrict__ zi,
    const float* __restrict__ gW, const float* __restrict__ gb)
{
  __shared__ float  sW[2048];        // gate_W (512 x 4)
  __shared__ int    s_cnt[NEXP];
  __shared__ double s_psum[NEXP];
  __shared__ int    s_base[NEXP];
  int tid = threadIdx.x;
  for (int i = tid; i < 2048; i += 256) sW[i] = gW[i];
  if (tid < NEXP) { s_cnt[tid] = 0; s_psum[tid] = 0.0; }
  __syncthreads();

  int lane = tid & 31, warp = tid >> 5;
  int row  = blockIdx.x * 8 + warp;
  const float4* zg4 = (const float4*)(zg + (size_t)row * 256);
  const float4* zi4 = (const float4*)(zi + (size_t)row * 256);
  float a0 = 0.f, a1 = 0.f, a2 = 0.f, a3 = 0.f;
  float4 xs[4];
  xs[0] = zg4[lane]; xs[1] = zg4[lane + 32];
  xs[2] = zi4[lane]; xs[3] = zi4[lane + 32];
  int dbase[4] = { 4 * lane, 128 + 4 * lane, 256 + 4 * lane, 384 + 4 * lane };
  #pragma unroll
  for (int q = 0; q < 4; q++) {
    const float* xv = (const float*)&xs[q];
    #pragma unroll
    for (int j = 0; j < 4; j++) {
      float x = xv[j];
      float4 w = *(const float4*)&sW[(dbase[q] + j) * 4];
      a0 += x * w.x; a1 += x * w.y; a2 += x * w.z; a3 += x * w.w;
    }
  }
  #pragma unroll
  for (int off = 16; off; off >>= 1) {
    a0 += __shfl_down_sync(0xffffffffu, a0, off);
    a1 += __shfl_down_sync(0xffffffffu, a1, off);
    a2 += __shfl_down_sync(0xffffffffu, a2, off);
    a3 += __shfl_down_sync(0xffffffffu, a3, off);
  }
  int myE = 0, myslot = 0;
  if (lane == 0) {
    float l0 = a0 + gb[0], l1 = a1 + gb[1], l2 = a2 + gb[2], l3 = a3 + gb[3];
    float m = fmaxf(fmaxf(l0, l1), fmaxf(l2, l3));
    float s = expf(l0 - m) + expf(l1 - m) + expf(l2 - m) + expf(l3 - m);
    int best = 0; float bl = l0;
    if (l1 > bl) { bl = l1; best = 1; }
    if (l2 > bl) { bl = l2; best = 2; }
    if (l3 > bl) { bl = l3; best = 3; }
    float p = expf(bl - m) / s;
    myslot = atomicAdd(&s_cnt[best], 1);
    atomicAdd(&s_psum[best], (double)p);
    myE = best;
  }
  __syncthreads();
  if (tid < NEXP) {
    s_base[tid] = atomicAdd(&g_count[tid], s_cnt[tid]);
    atomicAdd(&g_probsum[tid], s_psum[tid]);
  }
  __syncthreads();
  if (lane == 0) g_bucket[myE * B_ROWS + s_base[myE] + myslot] = row;
}

// ---------------- finalize: avg + aux loss --------------------------------
__global__ void k_finalize(float* out, int out_size) {
  int t = threadIdx.x;
  if (t < NEXP) {
    int c = g_count[t];
    g_avg[t] = (c > 0) ? (float)(g_probsum[t] / (double)c) : 0.f;
  }
  __syncthreads();
  if (t == 0) {
    float aux = 0.f;
    #pragma unroll
    for (int e = 0; e < NEXP; e++) {
      float u = (float)g_count[e] / (float)B_ROWS;
      aux += u * u;
    }
    aux *= (float)NEXP;
    if (out_size > B_ROWS * 256) out[(size_t)B_ROWS * 256] = aux;
  }
}

// ---------------- smem tiled GEMM: C(ROWSx256) = act(A(ROWSxK) @ W + b) ----
// 256 threads. Thread (rg=tid/32, cg=tid&31) computes rows rg*R..rg*R+R-1,
// cols cg+32*j (j=0..7). A broadcast reads; W chunk conflict-free reads.
template<int ROWS, int ACT>
__device__ __forceinline__ void tileGemm(
    const float* As, int pitchA, int Kdim,
    const float* __restrict__ Wg,    // Kdim x 256 row-major (gmem)
    const float* __restrict__ bias,  // 256
    float* Cs,                       // ROWS x 256 (smem)
    float* Wc)                       // 32 x 256 chunk (smem)
{
  constexpr int R = ROWS / 8;
  int tid = threadIdx.x;
  int cg = tid & 31;
  int rg = tid >> 5;
  float acc[R][8];
  #pragma unroll
  for (int r = 0; r < R; r++)
    #pragma unroll
    for (int j = 0; j < 8; j++) acc[r][j] = 0.f;

  for (int kc = 0; kc < Kdim; kc += 32) {
    __syncthreads();
    const float4* Wg4 = (const float4*)(Wg + (size_t)kc * 256);
    float4* Wc4 = (float4*)Wc;
    #pragma unroll
    for (int i = 0; i < 8; i++) Wc4[i * 256 + tid] = Wg4[i * 256 + tid];
    __syncthreads();
    #pragma unroll
    for (int k = 0; k < 32; k++) {
      float a[R];
      #pragma unroll
      for (int r = 0; r < R; r++) a[r] = As[(rg * R + r) * pitchA + kc + k];
      #pragma unroll
      for (int j = 0; j < 8; j++) {
        float w = Wc[k * 256 + cg + 32 * j];
        #pragma unroll
        for (int r = 0; r < R; r++) acc[r][j] = fmaf(a[r], w, acc[r][j]);
      }
    }
  }
  __syncthreads();
  #pragma unroll
  for (int j = 0; j < 8; j++) {
    int col = cg + 32 * j;
    float b = bias[col];
    #pragma unroll
    for (int r = 0; r < R; r++) {
      float v = acc[r][j] + b;
      if (ACT == 1) v = fmaxf(v, 0.f);
      if (ACT == 2) v = 1.f / (1.f + expf(-v));
      Cs[(rg * R + r) * 256 + col] = v;
    }
  }
  __syncthreads();
}

// ---------------- expert 0: concat ----------------------------------------
extern __shared__ float sm[];
__global__ void __launch_bounds__(256) k_concat(
    const float* __restrict__ zg, const float* __restrict__ zi,
    const float* __restrict__ W1, const float* __restrict__ b1,
    const float* __restrict__ W2, const float* __restrict__ b2,
    float* __restrict__ out)
{
  int cnt = g_count[0];
  int base = blockIdx.x * 32;
  if (base >= cnt) return;
  float avg = g_avg[0];
  float* Xs = sm;                   // 32*512
  float* Hs = Xs + 32 * 512;        // 32*256
  float* Os = Hs + 32 * 256;        // 32*256
  float* Wc = Os + 32 * 256;        // 32*256
  __shared__ int rows[32];
  int tid = threadIdx.x;
  if (tid < 32) {
    int i = base + tid;
    rows[tid] = (i < cnt) ? g_bucket[0 * B_ROWS + i] : -1;
  }
  __syncthreads();
  for (int i = tid; i < 32 * 512; i += 256) {
    int r = i >> 9, c = i & 511;
    int row = rows[r];
    float v = 0.f;
    if (row >= 0)
      v = (c < 256) ? zg[(size_t)row * 256 + c] : zi[(size_t)row * 256 + (c - 256)];
    Xs[i] = v;
  }
  __syncthreads();
  tileGemm<32, 1>(Xs, 512, 512, W1, b1, Hs, Wc);
  tileGemm<32, 0>(Hs, 256, 256, W2, b2, Os, Wc);
  for (int i = tid; i < 32 * 256; i += 256) {
    int row = rows[i >> 8];
    if (row >= 0) out[(size_t)row * 256 + (i & 255)] = avg * Os[i];
  }
}

// ---------------- expert 1: mul -------------------------------------------
__global__ void __launch_bounds__(256) k_mul(
    const float* __restrict__ zg, const float* __restrict__ zi,
    const float* __restrict__ W1, const float* __restrict__ b1,
    const float* __restrict__ W2, const float* __restrict__ b2,
    float* __restrict__ out)
{
  int cnt = g_count[1];
  int base = blockIdx.x * 32;
  if (base >= cnt) return;
  float avg = g_avg[1];
  float* Xs = sm;                   // 32*256
  float* Hs = Xs + 32 * 256;
  float* Os = Hs + 32 * 256;
  float* Wc = Os + 32 * 256;
  __shared__ int rows[32];
  int tid = threadIdx.x;
  if (tid < 32) {
    int i = base + tid;
    rows[tid] = (i < cnt) ? g_bucket[1 * B_ROWS + i] : -1;
  }
  __syncthreads();
  for (int i = tid; i < 32 * 256; i += 256) {
    int r = i >> 8, c = i & 255;
    int row = rows[r];
    float v = 0.f;
    if (row >= 0) v = zg[(size_t)row * 256 + c] * zi[(size_t)row * 256 + c];
    Xs[i] = v;
  }
  __syncthreads();
  tileGemm<32, 1>(Xs, 256, 256, W1, b1, Hs, Wc);
  tileGemm<32, 0>(Hs, 256, 256, W2, b2, Os, Wc);
  for (int i = tid; i < 32 * 256; i += 256) {
    int row = rows[i >> 8];
    if (row >= 0) out[(size_t)row * 256 + (i & 255)] = avg * Os[i];
  }
}

// ---------------- expert 3: wsum ------------------------------------------
__global__ void __launch_bounds__(256) k_wsum(
    const float* __restrict__ zg, const float* __restrict__ zi,
    const float* __restrict__ Wa, const float* __restrict__ ba,
    const float* __restrict__ Wo, const float* __restrict__ bo,
    float* __restrict__ out)
{
  int cnt = g_count[3];
  int base = blockIdx.x * 32;
  if (base >= cnt) return;
  float avg = g_avg[3];
  float* Xs = sm;                   // 32*512
  float* Hs = Xs + 32 * 512;        // 32*256 (alpha then h)
  float* Os = Hs + 32 * 256;
  float* Wc = Os + 32 * 256;
  __shared__ int rows[32];
  int tid = threadIdx.x;
  if (tid < 32) {
    int i = base + tid;
    rows[tid] = (i < cnt) ? g_bucket[3 * B_ROWS + i] : -1;
  }
  __syncthreads();
  for (int i = tid; i < 32 * 512; i += 256) {
    int r = i >> 9, c = i & 511;
    int row = rows[r];
    float v = 0.f;
    if (row >= 0)
      v = (c < 256) ? zg[(size_t)row * 256 + c] : zi[(size_t)row * 256 + (c - 256)];
    Xs[i] = v;
  }
  __syncthreads();
  tileGemm<32, 2>(Xs, 512, 512, Wa, ba, Hs, Wc);   // alpha = sigmoid(...)
  // h = alpha*zg + (1-alpha)*zi  (zg/zi live in Xs)
  for (int i = tid; i < 32 * 256; i += 256) {
    int r = i >> 8, c = i & 255;
    float a = Hs[i];
    Hs[i] = a * Xs[r * 512 + c] + (1.f - a) * Xs[r * 512 + 256 + c];
  }
  // tileGemm's leading __syncthreads covers the RAW above
  tileGemm<32, 0>(Hs, 256, 256, Wo, bo, Os, Wc);
  for (int i = tid; i < 32 * 256; i += 256) {
    int row = rows[i >> 8];
    if (row >= 0) out[(size_t)row * 256 + (i & 255)] = avg * Os[i];
  }
}

// ---------------- expert 2: attn ------------------------------------------
// 16 rows/tile -> 32 token-rows (token 2i = zg row, 2i+1 = zi row).
// mean(o@Wo+bo) = mean(o)@Wo+bo; per head mean(o) = c0*v0 + c1*v1,
// c_s = (a[0][s]+a[1][s])/2.
__global__ void __launch_bounds__(256) k_attn(
    const float* __restrict__ zg, const float* __restrict__ zi,
    const float* __restrict__ Wq, const float* __restrict__ bq,
    const float* __restrict__ Wk, const float* __restrict__ bk,
    const float* __restrict__ Wv, const float* __restrict__ bv,
    const float* __restrict__ Wo, const float* __restrict__ bo,
    const float* __restrict__ Wfc, const float* __restrict__ bfc,
    float* __restrict__ out)
{
  int cnt = g_count[2];
  int base = blockIdx.x * 16;
  if (base >= cnt) return;
  float avg = g_avg[2];
  float* Ts = sm;              // 32*256
  float* Qs = Ts + 8192;       // 32*256
  float* Ks = Qs + 8192;       // 32*256
  float* Vs = Ks + 8192;       // 32*256
  float* Wc = Vs + 8192;       // 32*256
  float* Ms = Wc + 8192;       // 16*256
  float* Os = Ms + 4096;       // 16*256
  float* Cf = Os + 4096;       // 16*8 coefs
  __shared__ int rows[16];
  int tid = threadIdx.x;
  if (tid < 16) {
    int i = base + tid;
    rows[tid] = (i < cnt) ? g_bucket[2 * B_ROWS + i] : -1;
  }
  __syncthreads();
  for (int i = tid; i < 32 * 256; i += 256) {
    int r = i >> 8, c = i & 255;
    int row = rows[r >> 1];
    float v = 0.f;
    if (row >= 0) v = (r & 1) ? zi[(size_t)row * 256 + c] : zg[(size_t)row * 256 + c];
    Ts[i] = v;
  }
  __syncthreads();
  tileGemm<32, 0>(Ts, 256, 256, Wq, bq, Qs, Wc);
  tileGemm<32, 0>(Ts, 256, 256, Wk, bk, Ks, Wc);
  tileGemm<32, 0>(Ts, 256, 256, Wv, bv, Vs, Wc);
  // scores + softmax -> per-head coefficients (warp w: rows 2w, 2w+1)
  {
    int warp = tid >> 5, lane = tid & 31;
    #pragma unroll
    for (int rr = 0; rr < 2; rr++) {
      int ri = warp * 2 + rr;
      #pragma unroll
      for (int h = 0; h < 4; h++) {
        float d00 = 0.f, d01 = 0.f, d10 = 0.f, d11 = 0.f;
        int cb = h * 64;
        #pragma unroll
        for (int u = 0; u < 2; u++) {
          int c = cb + lane + u * 32;
          float q0 = Qs[(2 * ri) * 256 + c], q1 = Qs[(2 * ri + 1) * 256 + c];
          float k0 = Ks[(2 * ri) * 256 + c], k1 = Ks[(2 * ri + 1) * 256 + c];
          d00 += q0 * k0; d01 += q0 * k1; d10 += q1 * k0; d11 += q1 * k1;
        }
        #pragma unroll
        for (int off = 16; off; off >>= 1) {
          d00 += __shfl_down_sync(0xffffffffu, d00, off);
          d01 += __shfl_down_sync(0xffffffffu, d01, off);
          d10 += __shfl_down_sync(0xffffffffu, d10, off);
          d11 += __shfl_down_sync(0xffffffffu, d11, off);
        }
        if (lane == 0) {
          const float s = 0.125f;  // 1/sqrt(64)
          d00 *= s; d01 *= s; d10 *= s; d11 *= s;
          float m0 = fmaxf(d00, d01), m1 = fmaxf(d10, d11);
          float e00 = expf(d00 - m0), e01 = expf(d01 - m0);
          float e10 = expf(d10 - m1), e11 = expf(d11 - m1);
          float i0 = 1.f / (e00 + e01), i1 = 1.f / (e10 + e11);
          Cf[ri * 8 + h * 2 + 0] = 0.5f * (e00 * i0 + e10 * i1);
          Cf[ri * 8 + h * 2 + 1] = 0.5f * (e01 * i0 + e11 * i1);
        }
      }
    }
  }
  __syncthreads();
  for (int i = tid; i < 16 * 256; i += 256) {
    int ri = i >> 8, c = i & 255, h = c >> 6;
    float c0 = Cf[ri * 8 + h * 2], c1 = Cf[ri * 8 + h * 2 + 1];
    Ms[i] = c0 * Vs[(2 * ri) * 256 + c] + c1 * Vs[(2 * ri + 1) * 256 + c];
  }
  tileGemm<16, 0>(Ms, 256, 256, Wo, bo, Os, Wc);
  tileGemm<16, 0>(Os, 256, 256, Wfc, bfc, Ms, Wc);  // final into Ms
  for (int i = tid; i < 16 * 256; i += 256) {
    int row = rows[i >> 8];
    if (row >= 0) out[(size_t)row * 256 + (i & 255)] = avg * Ms[i];
  }
}

// ---------------- launch ---------------------------------------------------
extern "C" void kernel_launch(void* const* d_in, const int* in_sizes, int n_in,
                              void* d_out, int out_size) {
  (void)in_sizes; (void)n_in;
  const float* zg  = (const float*)d_in[0];
  const float* zi  = (const float*)d_in[1];
  const float* gW  = (const float*)d_in[2];
  const float* gb  = (const float*)d_in[3];
  const float* cW1 = (const float*)d_in[4];
  const float* cb1 = (const float*)d_in[5];
  const float* cW2 = (const float*)d_in[6];
  const float* cb2 = (const float*)d_in[7];
  const float* mW1 = (const float*)d_in[8];
  const float* mb1 = (const float*)d_in[9];
  const float* mW2 = (const float*)d_in[10];
  const float* mb2 = (const float*)d_in[11];
  const float* aWq = (const float*)d_in[12];
  const float* abq = (const float*)d_in[13];
  const float* aWk = (const float*)d_in[14];
  const float* abk = (const float*)d_in[15];
  const float* aWv = (const float*)d_in[16];
  const float* abv = (const float*)d_in[17];
  const float* aWo = (const float*)d_in[18];
  const float* abo = (const float*)d_in[19];
  const float* aWfc = (const float*)d_in[20];
  const float* abfc = (const float*)d_in[21];
  const float* wWa = (const float*)d_in[22];
  const float* wba = (const float*)d_in[23];
  const float* wWo = (const float*)d_in[24];
  const float* wbo = (const float*)d_in[25];
  float* out = (float*)d_out;

  const int SM_CONCAT = 163840;  // 32*512 + 3*32*256 floats
  const int SM_MUL    = 131072;  // 4*32*256 floats
  const int SM_WSUM   = 163840;
  const int SM_ATTN   = 197120;  // 5*8192 + 2*4096 + 128 floats

  cudaFuncSetAttribute(k_concat, cudaFuncAttributeMaxDynamicSharedMemorySize, SM_CONCAT);
  cudaFuncSetAttribute(k_mul,    cudaFuncAttributeMaxDynamicSharedMemorySize, SM_MUL);
  cudaFuncSetAttribute(k_wsum,   cudaFuncAttributeMaxDynamicSharedMemorySize, SM_WSUM);
  cudaFuncSetAttribute(k_attn,   cudaFuncAttributeMaxDynamicSharedMemorySize, SM_ATTN);

  k_reset<<<1, 32>>>();
  k_gate<<<B_ROWS / 8, 256>>>(zg, zi, gW, gb);
  k_finalize<<<1, 32>>>(out, out_size);
  k_concat<<<B_ROWS / 32, 256, SM_CONCAT>>>(zg, zi, cW1, cb1, cW2, cb2, out);
  k_mul<<<B_ROWS / 32, 256, SM_MUL>>>(zg, zi, mW1, mb1, mW2, mb2, out);
  k_attn<<<B_ROWS / 16, 256, SM_ATTN>>>(zg, zi, aWq, abq, aWk, abk, aWv, abv,
                                        aWo, abo, aWfc, abfc, out);
  k_wsum<<<B_ROWS / 32, 256, SM_WSUM>>>(zg, zi, wWa, wba, wWo, wbo, out);
}

// round 5
// speedup vs baseline: 1.6819x; 1.6819x over previous
#include <cuda_runtime.h>
#include <math.h>

#define B_ROWS 131072
#define NEXP   4
#define THREADS 512

typedef unsigned long long ull;

// ---------------- device scratch ------------------------------------------
__device__ int    g_count[NEXP];
__device__ double g_probsum[NEXP];
__device__ float  g_avg[NEXP];
__device__ int    g_bucket[NEXP * B_ROWS];

// ---------------- f32x2 helpers -------------------------------------------
__device__ __forceinline__ ull fpack(float x, float y) {
  ull r; asm("mov.b64 %0, {%1, %2};" : "=l"(r) : "f"(x), "f"(y)); return r;
}
__device__ __forceinline__ ull fsplat(float x) {
  ull r; asm("mov.b64 %0, {%1, %1};" : "=l"(r) : "f"(x)); return r;
}
__device__ __forceinline__ void ffma2(ull& d, ull a, ull b) {
  asm("fma.rn.f32x2 %0, %1, %2, %0;" : "+l"(d) : "l"(a), "l"(b));
}
__device__ __forceinline__ float2 funpack(ull v) {
  float2 f; asm("mov.b64 {%0, %1}, %2;" : "=f"(f.x), "=f"(f.y) : "l"(v)); return f;
}

// ---------------- cp.async helpers ----------------------------------------
__device__ __forceinline__ void cp16(void* sdst, const void* gsrc) {
  unsigned s = (unsigned)__cvta_generic_to_shared(sdst);
  asm volatile("cp.async.cg.shared.global [%0], [%1], 16;\n" :: "r"(s), "l"(gsrc));
}
__device__ __forceinline__ void cp_commit() {
  asm volatile("cp.async.commit_group;\n" ::: "memory");
}
__device__ __forceinline__ void cp_wait1() {
  asm volatile("cp.async.wait_group 1;\n" ::: "memory");
}

// ---------------- staging --------------------------------------------------
// W chunk: 32 x 256 floats (32KB), contiguous.
__device__ __forceinline__ void stage_W(float* Wbuf, const float* Wg, int kc) {
  int t = threadIdx.x;
  const float4* src = (const float4*)(Wg + (size_t)kc * 256);
  #pragma unroll
  for (int i = 0; i < 4; i++)
    cp16(Wbuf + (i * 512 + t) * 4, src + i * 512 + t);
}
// A chunk: 64 rows x 32 floats (8KB), gathered via per-row pointers.
__device__ __forceinline__ void stage_A(float* Abuf, const float* const* ptab, int kcl) {
  int t = threadIdx.x;
  int r = t >> 3, seg = t & 7;
  cp16(Abuf + r * 32 + seg * 4, ptab[r] + kcl + seg * 4);
}

// ---------------- packed-FMA chunk kernel ----------------------------------
// acc[p][c] is f32x2 over rows (rbase+2p, rbase+2p+1), cols cg*4+c.
template<int NPAIR>
__device__ __forceinline__ void chunk_fma(
    const float* __restrict__ Ab, int apitch,
    const float* __restrict__ Wb,
    ull (&acc)[NPAIR][4], int rbase, int cg)
{
  #pragma unroll
  for (int k4 = 0; k4 < 8; k4++) {
    float4 a4[2 * NPAIR];
    #pragma unroll
    for (int r = 0; r < 2 * NPAIR; r++)
      a4[r] = *(const float4*)(Ab + (rbase + r) * apitch + k4 * 4);
    #pragma unroll
    for (int kk = 0; kk < 4; kk++) {
      float4 w = *(const float4*)(Wb + (k4 * 4 + kk) * 256 + (cg << 2));
      ull ws0 = fsplat(w.x), ws1 = fsplat(w.y), ws2 = fsplat(w.z), ws3 = fsplat(w.w);
      #pragma unroll
      for (int p = 0; p < NPAIR; p++) {
        const float* alo = (const float*)&a4[2 * p];
        const float* ahi = (const float*)&a4[2 * p + 1];
        ull ap = fpack(alo[kk], ahi[kk]);
        ffma2(acc[p][0], ap, ws0);
        ffma2(acc[p][1], ap, ws1);
        ffma2(acc[p][2], ap, ws2);
        ffma2(acc[p][3], ap, ws3);
      }
    }
  }
}

// ---------------- GEMM cores -----------------------------------------------
// 64-row, streamed (gathered) A + streamed W, K = NC*32.
template<int NC>
__device__ __forceinline__ void gemm_streamA(
    const float* const* ptab, const float* __restrict__ Wg,
    float* Abuf, float* Wbuf, ull (&acc)[4][4], int rbase, int cg)
{
  #pragma unroll
  for (int p = 0; p < 4; p++)
    #pragma unroll
    for (int c = 0; c < 4; c++) acc[p][c] = 0ULL;
  stage_A(Abuf, ptab, 0);                stage_W(Wbuf, Wg, 0);   cp_commit();
  stage_A(Abuf + 2048, ptab, 32);        stage_W(Wbuf + 8192, Wg, 32); cp_commit();
  for (int c = 0; c < NC; c++) {
    cp_wait1(); __syncthreads();
    chunk_fma<4>(Abuf + (c & 1) * 2048, 32, Wbuf + (c & 1) * 8192, acc, rbase, cg);
    __syncthreads();
    int cn = c + 2;
    if (cn < NC) {
      int kc = cn * 32;
      stage_A(Abuf + (cn & 1) * 2048, ptab + ((kc >> 8) << 6), kc & 255);
      stage_W(Wbuf + (cn & 1) * 8192, Wg, kc);
    }
    cp_commit();
  }
}

// A resident in smem (pitch 256), streamed W, K = NC*32.
template<int NPAIR, int NC>
__device__ __forceinline__ void gemm_smemA(
    const float* As, const float* __restrict__ Wg,
    float* Wbuf, ull (&acc)[NPAIR][4], int rbase, int cg)
{
  #pragma unroll
  for (int p = 0; p < NPAIR; p++)
    #pragma unroll
    for (int c = 0; c < 4; c++) acc[p][c] = 0ULL;
  stage_W(Wbuf, Wg, 0);        cp_commit();
  stage_W(Wbuf + 8192, Wg, 32); cp_commit();
  for (int c = 0; c < NC; c++) {
    cp_wait1(); __syncthreads();
    chunk_fma<NPAIR>(As + c * 32, 256, Wbuf + (c & 1) * 8192, acc, rbase, cg);
    __syncthreads();
    int cn = c + 2;
    if (cn < NC) stage_W(Wbuf + (cn & 1) * 8192, Wg, cn * 32);
    cp_commit();
  }
}

// ---------------- epilogues ------------------------------------------------
template<int NPAIR, int ACT>
__device__ __forceinline__ void epi_smem(
    ull (&acc)[NPAIR][4], const float* __restrict__ bias,
    float* Cs, int rbase, int cg)
{
  float4 b4 = *(const float4*)(bias + (cg << 2));
  #pragma unroll
  for (int p = 0; p < NPAIR; p++) {
    float2 v0 = funpack(acc[p][0]), v1 = funpack(acc[p][1]);
    float2 v2 = funpack(acc[p][2]), v3 = funpack(acc[p][3]);
    float4 lo = make_float4(v0.x + b4.x, v1.x + b4.y, v2.x + b4.z, v3.x + b4.w);
    float4 hi = make_float4(v0.y + b4.x, v1.y + b4.y, v2.y + b4.z, v3.y + b4.w);
    if (ACT == 1) {
      lo.x = fmaxf(lo.x, 0.f); lo.y = fmaxf(lo.y, 0.f); lo.z = fmaxf(lo.z, 0.f); lo.w = fmaxf(lo.w, 0.f);
      hi.x = fmaxf(hi.x, 0.f); hi.y = fmaxf(hi.y, 0.f); hi.z = fmaxf(hi.z, 0.f); hi.w = fmaxf(hi.w, 0.f);
    }
    if (ACT == 2) {
      lo.x = 1.f/(1.f+expf(-lo.x)); lo.y = 1.f/(1.f+expf(-lo.y));
      lo.z = 1.f/(1.f+expf(-lo.z)); lo.w = 1.f/(1.f+expf(-lo.w));
      hi.x = 1.f/(1.f+expf(-hi.x)); hi.y = 1.f/(1.f+expf(-hi.y));
      hi.z = 1.f/(1.f+expf(-hi.z)); hi.w = 1.f/(1.f+expf(-hi.w));
    }
    *(float4*)(Cs + (rbase + 2 * p) * 256 + (cg << 2)) = lo;
    *(float4*)(Cs + (rbase + 2 * p + 1) * 256 + (cg << 2)) = hi;
  }
  __syncthreads();
}

template<int NPAIR>
__device__ __forceinline__ void epi_gmem(
    ull (&acc)[NPAIR][4], const float* __restrict__ bias,
    float* __restrict__ out, const int* rows, int rbase, int cg, float avg)
{
  float4 b4 = *(const float4*)(bias + (cg << 2));
  #pragma unroll
  for (int p = 0; p < NPAIR; p++) {
    int r0 = rbase + 2 * p, r1 = r0 + 1;
    float2 v0 = funpack(acc[p][0]), v1 = funpack(acc[p][1]);
    float2 v2 = funpack(acc[p][2]), v3 = funpack(acc[p][3]);
    float4 lo = make_float4((v0.x + b4.x) * avg, (v1.x + b4.y) * avg,
                            (v2.x + b4.z) * avg, (v3.x + b4.w) * avg);
    float4 hi = make_float4((v0.y + b4.x) * avg, (v1.y + b4.y) * avg,
                            (v2.y + b4.z) * avg, (v3.y + b4.w) * avg);
    if (rows[r0] >= 0) *(float4*)(out + (size_t)rows[r0] * 256 + (cg << 2)) = lo;
    if (rows[r1] >= 0) *(float4*)(out + (size_t)rows[r1] * 256 + (cg << 2)) = hi;
  }
}

// ---------------- reset / gate / finalize ----------------------------------
__global__ void k_reset() {
  int t = threadIdx.x;
  if (t < NEXP) { g_count[t] = 0; g_probsum[t] = 0.0; }
}

__global__ void __launch_bounds__(256) k_gate(
    const float* __restrict__ zg, const float* __restrict__ zi,
    const float* __restrict__ gW, const float* __restrict__ gb)
{
  __shared__ float  sW[2048];
  __shared__ int    s_cnt[NEXP];
  __shared__ double s_psum[NEXP];
  __shared__ int    s_base[NEXP];
  int tid = threadIdx.x;
  for (int i = tid; i < 2048; i += 256) sW[i] = gW[i];
  if (tid < NEXP) { s_cnt[tid] = 0; s_psum[tid] = 0.0; }
  __syncthreads();

  int lane = tid & 31, warp = tid >> 5;
  int row  = blockIdx.x * 8 + warp;
  const float4* zg4 = (const float4*)(zg + (size_t)row * 256);
  const float4* zi4 = (const float4*)(zi + (size_t)row * 256);
  float a0 = 0.f, a1 = 0.f, a2 = 0.f, a3 = 0.f;
  float4 xs[4];
  xs[0] = zg4[lane]; xs[1] = zg4[lane + 32];
  xs[2] = zi4[lane]; xs[3] = zi4[lane + 32];
  int dbase[4] = { 4 * lane, 128 + 4 * lane, 256 + 4 * lane, 384 + 4 * lane };
  #pragma unroll
  for (int q = 0; q < 4; q++) {
    const float* xv = (const float*)&xs[q];
    #pragma unroll
    for (int j = 0; j < 4; j++) {
      float x = xv[j];
      float4 w = *(const float4*)&sW[(dbase[q] + j) * 4];
      a0 += x * w.x; a1 += x * w.y; a2 += x * w.z; a3 += x * w.w;
    }
  }
  #pragma unroll
  for (int off = 16; off; off >>= 1) {
    a0 += __shfl_down_sync(0xffffffffu, a0, off);
    a1 += __shfl_down_sync(0xffffffffu, a1, off);
    a2 += __shfl_down_sync(0xffffffffu, a2, off);
    a3 += __shfl_down_sync(0xffffffffu, a3, off);
  }
  int myE = 0, myslot = 0;
  if (lane == 0) {
    float l0 = a0 + gb[0], l1 = a1 + gb[1], l2 = a2 + gb[2], l3 = a3 + gb[3];
    float m = fmaxf(fmaxf(l0, l1), fmaxf(l2, l3));
    float s = expf(l0 - m) + expf(l1 - m) + expf(l2 - m) + expf(l3 - m);
    int best = 0; float bl = l0;
    if (l1 > bl) { bl = l1; best = 1; }
    if (l2 > bl) { bl = l2; best = 2; }
    if (l3 > bl) { bl = l3; best = 3; }
    float p = expf(bl - m) / s;
    myslot = atomicAdd(&s_cnt[best], 1);
    atomicAdd(&s_psum[best], (double)p);
    myE = best;
  }
  __syncthreads();
  if (tid < NEXP) {
    s_base[tid] = atomicAdd(&g_count[tid], s_cnt[tid]);
    atomicAdd(&g_probsum[tid], s_psum[tid]);
  }
  __syncthreads();
  if (lane == 0) g_bucket[myE * B_ROWS + s_base[myE] + myslot] = row;
}

__global__ void k_finalize(float* out, int out_size) {
  int t = threadIdx.x;
  if (t < NEXP) {
    int c = g_count[t];
    g_avg[t] = (c > 0) ? (float)(g_probsum[t] / (double)c) : 0.f;
  }
  __syncthreads();
  if (t == 0) {
    float aux = 0.f;
    #pragma unroll
    for (int e = 0; e < NEXP; e++) {
      float u = (float)g_count[e] / (float)B_ROWS;
      aux += u * u;
    }
    aux *= (float)NEXP;
    if (out_size > B_ROWS * 256) out[(size_t)B_ROWS * 256] = aux;
  }
}

// ---------------- expert kernels -------------------------------------------
extern __shared__ float sm[];

// concat: H = relu([zg,zi] @ W1 + b1); O = H @ W2 + b2
__global__ void __launch_bounds__(THREADS, 1) k_concat(
    const float* __restrict__ zg, const float* __restrict__ zi,
    const float* __restrict__ W1, const float* __restrict__ b1,
    const float* __restrict__ W2, const float* __restrict__ b2,
    float* __restrict__ out)
{
  int cnt = g_count[0];
  int base = blockIdx.x * 64;
  if (base >= cnt) return;
  float avg = g_avg[0];
  float* Hs   = sm;            // 64*256
  float* Abuf = sm + 16384;    // 2*2048
  float* Wbuf = sm + 20480;    // 2*8192
  __shared__ int rows[64];
  __shared__ const float* ptab[128];
  int tid = threadIdx.x;
  int cg = tid & 63, rg = tid >> 6, rbase = rg << 3;
  if (tid < 64) {
    int i = base + tid;
    int row = (i < cnt) ? g_bucket[0 * B_ROWS + i] : -1;
    rows[tid] = row;
    size_t rr = (size_t)(row < 0 ? 0 : row) * 256;
    ptab[tid]      = zg + rr;
    ptab[64 + tid] = zi + rr;   // FIX: kcl already carries the -256
  }
  __syncthreads();
  ull acc[4][4];
  gemm_streamA<16>(ptab, W1, Abuf, Wbuf, acc, rbase, cg);
  epi_smem<4, 1>(acc, b1, Hs, rbase, cg);
  gemm_smemA<4, 8>(Hs, W2, Wbuf, acc, rbase, cg);
  epi_gmem<4>(acc, b2, out, rows, rbase, cg, avg);
}

// mul: H = relu((zg*zi) @ W1 + b1); O = H @ W2 + b2
__global__ void __launch_bounds__(THREADS, 1) k_mul(
    const float* __restrict__ zg, const float* __restrict__ zi,
    const float* __restrict__ W1, const float* __restrict__ b1,
    const float* __restrict__ W2, const float* __restrict__ b2,
    float* __restrict__ out)
{
  int cnt = g_count[1];
  int base = blockIdx.x * 64;
  if (base >= cnt) return;
  float avg = g_avg[1];
  float* Xs   = sm;            // 64*256
  float* Hs   = sm + 16384;    // 64*256
  float* Wbuf = sm + 32768;    // 2*8192
  __shared__ int rows[64];
  int tid = threadIdx.x;
  int cg = tid & 63, rg = tid >> 6, rbase = rg << 3;
  if (tid < 64) {
    int i = base + tid;
    rows[tid] = (i < cnt) ? g_bucket[1 * B_ROWS + i] : -1;
  }
  __syncthreads();
  const float4* zg4 = (const float4*)zg;
  const float4* zi4 = (const float4*)zi;
  float4* Xs4 = (float4*)Xs;
  for (int i = tid; i < 64 * 64; i += THREADS) {
    int r = i >> 6, c4 = i & 63;
    int row = rows[r];
    float4 v = make_float4(0.f, 0.f, 0.f, 0.f);
    if (row >= 0) {
      float4 g = zg4[(size_t)row * 64 + c4];
      float4 z = zi4[(size_t)row * 64 + c4];
      v = make_float4(g.x * z.x, g.y * z.y, g.z * z.z, g.w * z.w);
    }
    Xs4[i] = v;
  }
  __syncthreads();
  ull acc[4][4];
  gemm_smemA<4, 8>(Xs, W1, Wbuf, acc, rbase, cg);
  epi_smem<4, 1>(acc, b1, Hs, rbase, cg);
  gemm_smemA<4, 8>(Hs, W2, Wbuf, acc, rbase, cg);
  epi_gmem<4>(acc, b2, out, rows, rbase, cg, avg);
}

// wsum: alpha = sigmoid([zg,zi] @ Wa + ba); h = alpha*zg + (1-alpha)*zi; O = h @ Wo + bo
__global__ void __launch_bounds__(THREADS, 1) k_wsum(
    const float* __restrict__ zg, const float* __restrict__ zi,
    const float* __restrict__ Wa, const float* __restrict__ ba,
    const float* __restrict__ Wo, const float* __restrict__ bo,
    float* __restrict__ out)
{
  int cnt = g_count[3];
  int base = blockIdx.x * 64;
  if (base >= cnt) return;
  float avg = g_avg[3];
  float* Hs   = sm;            // 64*256
  float* Abuf = sm + 16384;
  float* Wbuf = sm + 20480;
  __shared__ int rows[64];
  __shared__ const float* ptab[128];
  int tid = threadIdx.x;
  int cg = tid & 63, rg = tid >> 6, rbase = rg << 3;
  if (tid < 64) {
    int i = base + tid;
    int row = (i < cnt) ? g_bucket[3 * B_ROWS + i] : -1;
    rows[tid] = row;
    size_t rr = (size_t)(row < 0 ? 0 : row) * 256;
    ptab[tid]      = zg + rr;
    ptab[64 + tid] = zi + rr;   // FIX
  }
  __syncthreads();
  ull acc[4][4];
  gemm_streamA<16>(ptab, Wa, Abuf, Wbuf, acc, rbase, cg);
  epi_smem<4, 2>(acc, ba, Hs, rbase, cg);   // alpha (sigmoid)
  // h = alpha*zg + (1-alpha)*zi, in place
  const float4* zg4 = (const float4*)zg;
  const float4* zi4 = (const float4*)zi;
  float4* Hs4 = (float4*)Hs;
  for (int i = tid; i < 64 * 64; i += THREADS) {
    int r = i >> 6, c4 = i & 63;
    int row = rows[r];
    float4 h = make_float4(0.f, 0.f, 0.f, 0.f);
    if (row >= 0) {
      float4 a = Hs4[i];
      float4 g = zg4[(size_t)row * 64 + c4];
      float4 z = zi4[(size_t)row * 64 + c4];
      h = make_float4(a.x * g.x + (1.f - a.x) * z.x,
                      a.y * g.y + (1.f - a.y) * z.y,
                      a.z * g.z + (1.f - a.z) * z.z,
                      a.w * g.w + (1.f - a.w) * z.w);
    }
    Hs4[i] = h;
  }
  __syncthreads();
  ull acc2[4][4];
  gemm_smemA<4, 8>(Hs, Wo, Wbuf, acc2, rbase, cg);
  epi_gmem<4>(acc2, bo, out, rows, rbase, cg, avg);
}

// attn: QKV over 64 token rows (32 pairs), pair-softmax -> coefs, V-combine,
// then 2 chained 256x256 GEMMs on the 32 combined rows.
__global__ void __launch_bounds__(THREADS, 1) k_attn(
    const float* __restrict__ zg, const float* __restrict__ zi,
    const float* __restrict__ Wq, const float* __restrict__ bq,
    const float* __restrict__ Wk, const float* __restrict__ bk,
    const float* __restrict__ Wv, const float* __restrict__ bv,
    const float* __restrict__ Wo, const float* __restrict__ bo,
    const float* __restrict__ Wfc, const float* __restrict__ bfc,
    float* __restrict__ out)
{
  int cnt = g_count[2];
  int base = blockIdx.x * 32;
  if (base >= cnt) return;
  float avg = g_avg[2];
  float* Qs   = sm;            // 64*256 (later Ms 32*256)
  float* Ks   = sm + 16384;    // 64*256 (later Os 32*256)
  float* Abuf = sm + 32768;    // 2*2048
  float* Wbuf = sm + 36864;    // 2*8192
  __shared__ int rows[32];
  __shared__ const float* ptab[64];
  __shared__ float Cf[32 * 8];
  int tid = threadIdx.x;
  int cg = tid & 63, rg = tid >> 6;
  int rbase = rg << 3;        // for 64-row GEMMs
  if (tid < 64) {
    int pair = tid >> 1;
    int i = base + pair;
    int row = (i < cnt) ? g_bucket[2 * B_ROWS + i] : -1;
    if ((tid & 1) == 0) rows[pair] = row;
    size_t rr = (size_t)(row < 0 ? 0 : row) * 256;
    ptab[tid] = ((tid & 1) ? zi : zg) + rr;
  }
  __syncthreads();

  ull acc[4][4];
  gemm_streamA<8>(ptab, Wq, Abuf, Wbuf, acc, rbase, cg);
  epi_smem<4, 0>(acc, bq, Qs, rbase, cg);
  gemm_streamA<8>(ptab, Wk, Abuf, Wbuf, acc, rbase, cg);
  epi_smem<4, 0>(acc, bk, Ks, rbase, cg);

  // scores + softmax -> per-head pair coefficients. 16 warps x 2 pairs.
  {
    int warp = tid >> 5, lane = tid & 31;
    #pragma unroll
    for (int rr = 0; rr < 2; rr++) {
      int pair = warp * 2 + rr;
      #pragma unroll
      for (int h = 0; h < 4; h++) {
        float d00 = 0.f, d01 = 0.f, d10 = 0.f, d11 = 0.f;
        int cb = h * 64;
        #pragma unroll
        for (int u = 0; u < 2; u++) {
          int c = cb + lane + u * 32;
          float q0 = Qs[(2 * pair) * 256 + c], q1 = Qs[(2 * pair + 1) * 256 + c];
          float k0 = Ks[(2 * pair) * 256 + c], k1 = Ks[(2 * pair + 1) * 256 + c];
          d00 += q0 * k0; d01 += q0 * k1; d10 += q1 * k0; d11 += q1 * k1;
        }
        #pragma unroll
        for (int off = 16; off; off >>= 1) {
          d00 += __shfl_down_sync(0xffffffffu, d00, off);
          d01 += __shfl_down_sync(0xffffffffu, d01, off);
          d10 += __shfl_down_sync(0xffffffffu, d10, off);
          d11 += __shfl_down_sync(0xffffffffu, d11, off);
        }
        if (lane == 0) {
          const float s = 0.125f;  // 1/sqrt(64)
          d00 *= s; d01 *= s; d10 *= s; d11 *= s;
          float m0 = fmaxf(d00, d01), m1 = fmaxf(d10, d11);
          float e00 = expf(d00 - m0), e01 = expf(d01 - m0);
          float e10 = expf(d10 - m1), e11 = expf(d11 - m1);
          float i0 = 1.f / (e00 + e01), i1 = 1.f / (e10 + e11);
          Cf[pair * 8 + h * 2 + 0] = 0.5f * (e00 * i0 + e10 * i1);
          Cf[pair * 8 + h * 2 + 1] = 0.5f * (e01 * i0 + e11 * i1);
        }
      }
    }
  }
  __syncthreads();

  // V GEMM with pair-combine epilogue -> Ms (= Qs region)
  gemm_streamA<8>(ptab, Wv, Abuf, Wbuf, acc, rbase, cg);
  {
    float* Ms = Qs;
    float4 b4 = *(const float4*)(bv + (cg << 2));
    int head = cg >> 4;      // col group cg*4 -> head (cg*4)/64
    #pragma unroll
    for (int p = 0; p < 4; p++) {
      int pair = rg * 4 + p;
      float c0 = Cf[pair * 8 + head * 2 + 0];
      float c1 = Cf[pair * 8 + head * 2 + 1];
      float2 v0 = funpack(acc[p][0]), v1 = funpack(acc[p][1]);
      float2 v2 = funpack(acc[p][2]), v3 = funpack(acc[p][3]);
      float4 m = make_float4(
        c0 * (v0.x + b4.x) + c1 * (v0.y + b4.x),
        c0 * (v1.x + b4.y) + c1 * (v1.y + b4.y),
        c0 * (v2.x + b4.z) + c1 * (v2.y + b4.z),
        c0 * (v3.x + b4.w) + c1 * (v3.y + b4.w));
      *(float4*)(Ms + pair * 256 + (cg << 2)) = m;
    }
  }
  __syncthreads();

  // O = Ms @ Wo + bo   (32 rows)
  int rbase2 = rg << 2;
  ull acc2[2][4];
  gemm_smemA<2, 8>(Qs, Wo, Wbuf, acc2, rbase2, cg);
  epi_smem<2, 0>(acc2, bo, Ks, rbase2, cg);   // Os = Ks region
  // final = Os @ Wfc + bfc -> gmem
  gemm_smemA<2, 8>(Ks, Wfc, Wbuf, acc2, rbase2, cg);
  epi_gmem<2>(acc2, bfc, out, rows, rbase2, cg, avg);
}

// ---------------- launch ---------------------------------------------------
extern "C" void kernel_launch(void* const* d_in, const int* in_sizes, int n_in,
                              void* d_out, int out_size) {
  (void)in_sizes; (void)n_in;
  const float* zg  = (const float*)d_in[0];
  const float* zi  = (const float*)d_in[1];
  const float* gW  = (const float*)d_in[2];
  const float* gb  = (const float*)d_in[3];
  const float* cW1 = (const float*)d_in[4];
  const float* cb1 = (const float*)d_in[5];
  const float* cW2 = (const float*)d_in[6];
  const float* cb2 = (const float*)d_in[7];
  const float* mW1 = (const float*)d_in[8];
  const float* mb1 = (const float*)d_in[9];
  const float* mW2 = (const float*)d_in[10];
  const float* mb2 = (const float*)d_in[11];
  const float* aWq = (const float*)d_in[12];
  const float* abq = (const float*)d_in[13];
  const float* aWk = (const float*)d_in[14];
  const float* abk = (const float*)d_in[15];
  const float* aWv = (const float*)d_in[16];
  const float* abv = (const float*)d_in[17];
  const float* aWo = (const float*)d_in[18];
  const float* abo = (const float*)d_in[19];
  const float* aWfc = (const float*)d_in[20];
  const float* abfc = (const float*)d_in[21];
  const float* wWa = (const float*)d_in[22];
  const float* wba = (const float*)d_in[23];
  const float* wWo = (const float*)d_in[24];
  const float* wbo = (const float*)d_in[25];
  float* out = (float*)d_out;

  const int SM_CONCAT = 36864 * 4;   // Hs + Abuf + Wbuf
  const int SM_MUL    = 49152 * 4;   // Xs + Hs + Wbuf
  const int SM_WSUM   = 36864 * 4;
  const int SM_ATTN   = 53248 * 4;   // Qs + Ks + Abuf + Wbuf

  cudaFuncSetAttribute(k_concat, cudaFuncAttributeMaxDynamicSharedMemorySize, SM_CONCAT);
  cudaFuncSetAttribute(k_mul,    cudaFuncAttributeMaxDynamicSharedMemorySize, SM_MUL);
  cudaFuncSetAttribute(k_wsum,   cudaFuncAttributeMaxDynamicSharedMemorySize, SM_WSUM);
  cudaFuncSetAttribute(k_attn,   cudaFuncAttributeMaxDynamicSharedMemorySize, SM_ATTN);

  k_reset<<<1, 32>>>();
  k_gate<<<B_ROWS / 8, 256>>>(zg, zi, gW, gb);
  k_finalize<<<1, 32>>>(out, out_size);
  k_concat<<<B_ROWS / 64, THREADS, SM_CONCAT>>>(zg, zi, cW1, cb1, cW2, cb2, out);
  k_mul<<<B_ROWS / 64, THREADS, SM_MUL>>>(zg, zi, mW1, mb1, mW2, mb2, out);
  k_attn<<<B_ROWS / 32, THREADS, SM_ATTN>>>(zg, zi, aWq, abq, aWk, abk, aWv, abv,
                                            aWo, abo, aWfc, abfc, out);
  k_wsum<<<B_ROWS / 64, THREADS, SM_WSUM>>>(zg, zi, wWa, wba, wWo, wbo, out);
}

// round 6
// speedup vs baseline: 1.8137x; 1.0784x over previous
#include <cuda_runtime.h>
#include <math.h>

#define B_ROWS 131072
#define NEXP   4
#define THREADS 512

typedef unsigned long long ull;

// ---------------- device scratch ------------------------------------------
__device__ int    g_count[NEXP];
__device__ double g_probsum[NEXP];
__device__ float  g_avg[NEXP];
__device__ int    g_bucket[NEXP * B_ROWS];

// ---------------- f32x2 helpers -------------------------------------------
__device__ __forceinline__ void ffma2(ull& d, ull a, ull b) {
  asm("fma.rn.f32x2 %0, %1, %2, %0;" : "+l"(d) : "l"(a), "l"(b));
}
__device__ __forceinline__ float2 funpack(ull v) {
  float2 f; asm("mov.b64 {%0, %1}, %2;" : "=f"(f.x), "=f"(f.y) : "l"(v)); return f;
}

// ---------------- cp.async helpers ----------------------------------------
__device__ __forceinline__ void cp16(void* sdst, const void* gsrc) {
  unsigned s = (unsigned)__cvta_generic_to_shared(sdst);
  asm volatile("cp.async.cg.shared.global [%0], [%1], 16;\n" :: "r"(s), "l"(gsrc));
}
__device__ __forceinline__ void cp_commit() {
  asm volatile("cp.async.commit_group;\n" ::: "memory");
}
__device__ __forceinline__ void cp_wait1() {
  asm volatile("cp.async.wait_group 1;\n" ::: "memory");
}

// W chunk: 32 x 256 floats (32KB), contiguous.
__device__ __forceinline__ void stage_W(float* Wbuf, const float* Wg, int kc) {
  int t = threadIdx.x;
  const float4* src = (const float4*)(Wg + (size_t)kc * 256);
  #pragma unroll
  for (int i = 0; i < 4; i++)
    cp16(Wbuf + (i * 512 + t) * 4, src + i * 512 + t);
}

// ---------------- packed-FMA chunk: zero-mov inner loop --------------------
// acc[r][cp] is f32x2 over cols (col0+64*cp, col0+64*cp+1), row rbase+r.
// Adup: [rows][32] ull, each = (a,a).  Wb: [32][256] floats.
template<int NR>
__device__ __forceinline__ void chunk2(
    const ull* __restrict__ Adup, const float* __restrict__ Wb,
    ull (&acc)[NR][2], int rbase, int col0)
{
  #pragma unroll
  for (int k2 = 0; k2 < 16; k2++) {
    ulonglong2 a[NR];
    #pragma unroll
    for (int r = 0; r < NR; r++)
      a[r] = *(const ulonglong2*)(Adup + (rbase + r) * 32 + k2 * 2);
    #pragma unroll
    for (int kk = 0; kk < 2; kk++) {
      int k = k2 * 2 + kk;
      ull w0 = *(const ull*)(Wb + k * 256 + col0);
      ull w1 = *(const ull*)(Wb + k * 256 + col0 + 64);
      #pragma unroll
      for (int r = 0; r < NR; r++) {
        ull av = kk ? a[r].y : a[r].x;
        ffma2(acc[r][0], av, w0);
        ffma2(acc[r][1], av, w1);
      }
    }
  }
}

// ---------------- GEMM cores -----------------------------------------------
// Gathered A (LDG prefetch pipeline) + cp.async W. 64 rows, K = NC*32.
template<int NC>
__device__ __forceinline__ void gemm_streamA2(
    const float* const* ptab, const float* __restrict__ Wg,
    ull* Adup, float* Wbuf, ull (&acc)[8][2], int rbase, int col0)
{
  #pragma unroll
  for (int r = 0; r < 8; r++) { acc[r][0] = 0ULL; acc[r][1] = 0ULL; }
  int t = threadIdx.x;
  int ar = t >> 3, ak = (t & 7) * 4;
  float4 av = *(const float4*)(ptab[ar] + ak);
  stage_W(Wbuf, Wg, 0);         cp_commit();
  stage_W(Wbuf + 8192, Wg, 32); cp_commit();
  for (int c = 0; c < NC; c++) {
    // duplicate-store A chunk c
    float4* d = (float4*)(Adup + ar * 32 + ak);
    d[0] = make_float4(av.x, av.x, av.y, av.y);
    d[1] = make_float4(av.z, av.z, av.w, av.w);
    // prefetch A chunk c+1 (overlaps wait + compute)
    int cn = c + 1;
    if (cn < NC) {
      int kc = cn * 32;
      av = *(const float4*)(ptab[((kc >> 8) << 6) + ar] + (kc & 255) + ak);
    }
    cp_wait1(); __syncthreads();
    chunk2<8>(Adup, Wbuf + (c & 1) * 8192, acc, rbase, col0);
    __syncthreads();
    if (c + 2 < NC) stage_W(Wbuf + (c & 1) * 8192, Wg, (c + 2) * 32);
    cp_commit();
  }
}

// A resident in smem row-major (pitch 256), K = NC*32. Tile rows = NR*8.
template<int NR, int NC>
__device__ __forceinline__ void gemm_smemA2(
    const float* __restrict__ As, const float* __restrict__ Wg,
    ull* Adup, float* Wbuf, ull (&acc)[NR][2], int rbase, int col0)
{
  #pragma unroll
  for (int r = 0; r < NR; r++) { acc[r][0] = 0ULL; acc[r][1] = 0ULL; }
  int t = threadIdx.x;
  constexpr int ROWS = NR * 8;
  int ar = t >> 3, ak = (t & 7) * 4;
  stage_W(Wbuf, Wg, 0);         cp_commit();
  stage_W(Wbuf + 8192, Wg, 32); cp_commit();
  for (int c = 0; c < NC; c++) {
    if (ar < ROWS) {
      float4 av = *(const float4*)(As + ar * 256 + c * 32 + ak);
      float4* d = (float4*)(Adup + ar * 32 + ak);
      d[0] = make_float4(av.x, av.x, av.y, av.y);
      d[1] = make_float4(av.z, av.z, av.w, av.w);
    }
    cp_wait1(); __syncthreads();
    chunk2<NR>(Adup, Wbuf + (c & 1) * 8192, acc, rbase, col0);
    __syncthreads();
    if (c + 2 < NC) stage_W(Wbuf + (c & 1) * 8192, Wg, (c + 2) * 32);
    cp_commit();
  }
}

// ---------------- epilogues ------------------------------------------------
template<int NR, int ACT>
__device__ __forceinline__ void epi_smem2(
    ull (&acc)[NR][2], const float* __restrict__ bias,
    float* Cs, int rbase, int col0)
{
  float2 b0 = *(const float2*)(bias + col0);
  float2 b1 = *(const float2*)(bias + col0 + 64);
  #pragma unroll
  for (int r = 0; r < NR; r++) {
    #pragma unroll
    for (int cp = 0; cp < 2; cp++) {
      float2 v = funpack(acc[r][cp]);
      float2 b = cp ? b1 : b0;
      v.x += b.x; v.y += b.y;
      if (ACT == 1) { v.x = fmaxf(v.x, 0.f); v.y = fmaxf(v.y, 0.f); }
      if (ACT == 2) { v.x = 1.f/(1.f+expf(-v.x)); v.y = 1.f/(1.f+expf(-v.y)); }
      *(float2*)(Cs + (rbase + r) * 256 + col0 + cp * 64) = v;
    }
  }
  __syncthreads();
}

template<int NR>
__device__ __forceinline__ void epi_gmem2(
    ull (&acc)[NR][2], const float* __restrict__ bias,
    float* __restrict__ out, const int* rows, int rbase, int col0, float avg)
{
  float2 b0 = *(const float2*)(bias + col0);
  float2 b1 = *(const float2*)(bias + col0 + 64);
  #pragma unroll
  for (int r = 0; r < NR; r++) {
    int row = rows[rbase + r];
    if (row < 0) continue;
    #pragma unroll
    for (int cp = 0; cp < 2; cp++) {
      float2 v = funpack(acc[r][cp]);
      float2 b = cp ? b1 : b0;
      v.x = (v.x + b.x) * avg; v.y = (v.y + b.y) * avg;
      *(float2*)(out + (size_t)row * 256 + col0 + cp * 64) = v;
    }
  }
}

// ---------------- reset / gate / finalize ----------------------------------
__global__ void k_reset() {
  int t = threadIdx.x;
  if (t < NEXP) { g_count[t] = 0; g_probsum[t] = 0.0; }
}

__global__ void __launch_bounds__(256) k_gate(
    const float* __restrict__ zg, const float* __restrict__ zi,
    const float* __restrict__ gW, const float* __restrict__ gb)
{
  __shared__ float  sW[2048];
  __shared__ int    s_cnt[NEXP];
  __shared__ double s_psum[NEXP];
  __shared__ int    s_base[NEXP];
  int tid = threadIdx.x;
  for (int i = tid; i < 2048; i += 256) sW[i] = gW[i];
  if (tid < NEXP) { s_cnt[tid] = 0; s_psum[tid] = 0.0; }
  __syncthreads();

  int lane = tid & 31, warp = tid >> 5;
  int row  = blockIdx.x * 8 + warp;
  const float4* zg4 = (const float4*)(zg + (size_t)row * 256);
  const float4* zi4 = (const float4*)(zi + (size_t)row * 256);
  float a0 = 0.f, a1 = 0.f, a2 = 0.f, a3 = 0.f;
  float4 xs[4];
  xs[0] = zg4[lane]; xs[1] = zg4[lane + 32];
  xs[2] = zi4[lane]; xs[3] = zi4[lane + 32];
  int dbase[4] = { 4 * lane, 128 + 4 * lane, 256 + 4 * lane, 384 + 4 * lane };
  #pragma unroll
  for (int q = 0; q < 4; q++) {
    const float* xv = (const float*)&xs[q];
    #pragma unroll
    for (int j = 0; j < 4; j++) {
      float x = xv[j];
      float4 w = *(const float4*)&sW[(dbase[q] + j) * 4];
      a0 += x * w.x; a1 += x * w.y; a2 += x * w.z; a3 += x * w.w;
    }
  }
  #pragma unroll
  for (int off = 16; off; off >>= 1) {
    a0 += __shfl_down_sync(0xffffffffu, a0, off);
    a1 += __shfl_down_sync(0xffffffffu, a1, off);
    a2 += __shfl_down_sync(0xffffffffu, a2, off);
    a3 += __shfl_down_sync(0xffffffffu, a3, off);
  }
  int myE = 0, myslot = 0;
  if (lane == 0) {
    float l0 = a0 + gb[0], l1 = a1 + gb[1], l2 = a2 + gb[2], l3 = a3 + gb[3];
    float m = fmaxf(fmaxf(l0, l1), fmaxf(l2, l3));
    float s = expf(l0 - m) + expf(l1 - m) + expf(l2 - m) + expf(l3 - m);
    int best = 0; float bl = l0;
    if (l1 > bl) { bl = l1; best = 1; }
    if (l2 > bl) { bl = l2; best = 2; }
    if (l3 > bl) { bl = l3; best = 3; }
    float p = expf(bl - m) / s;
    myslot = atomicAdd(&s_cnt[best], 1);
    atomicAdd(&s_psum[best], (double)p);
    myE = best;
  }
  __syncthreads();
  if (tid < NEXP) {
    s_base[tid] = atomicAdd(&g_count[tid], s_cnt[tid]);
    atomicAdd(&g_probsum[tid], s_psum[tid]);
  }
  __syncthreads();
  if (lane == 0) g_bucket[myE * B_ROWS + s_base[myE] + myslot] = row;
}

__global__ void k_finalize(float* out, int out_size) {
  int t = threadIdx.x;
  if (t < NEXP) {
    int c = g_count[t];
    g_avg[t] = (c > 0) ? (float)(g_probsum[t] / (double)c) : 0.f;
  }
  __syncthreads();
  if (t == 0) {
    float aux = 0.f;
    #pragma unroll
    for (int e = 0; e < NEXP; e++) {
      float u = (float)g_count[e] / (float)B_ROWS;
      aux += u * u;
    }
    aux *= (float)NEXP;
    if (out_size > B_ROWS * 256) out[(size_t)B_ROWS * 256] = aux;
  }
}

// ---------------- expert kernels -------------------------------------------
extern __shared__ float sm[];

// thread-mapping helpers: rg = tid>>6 (8 groups), cgl = tid&31, cgh = (tid>>5)&1
#define TMAP() \
  int tid = threadIdx.x; \
  int rg = tid >> 6; \
  int cgl = tid & 31, cgh = (tid >> 5) & 1; \
  int col0 = 2 * cgl + 128 * cgh;

// concat: H = relu([zg,zi] @ W1 + b1); O = H @ W2 + b2
__global__ void __launch_bounds__(THREADS, 1) k_concat(
    const float* __restrict__ zg, const float* __restrict__ zi,
    const float* __restrict__ W1, const float* __restrict__ b1,
    const float* __restrict__ W2, const float* __restrict__ b2,
    float* __restrict__ out)
{
  int cnt = g_count[0];
  int base = blockIdx.x * 64;
  if (base >= cnt) return;
  float avg = g_avg[0];
  float* Hs   = sm;                    // 16384 floats
  float* Wbuf = sm + 16384;            // 16384 floats
  ull*   Adup = (ull*)(sm + 32768);    // 2048 ull
  __shared__ int rows[64];
  __shared__ const float* ptab[128];
  TMAP();
  int rbase = rg << 3;
  if (tid < 64) {
    int i = base + tid;
    int row = (i < cnt) ? g_bucket[0 * B_ROWS + i] : -1;
    rows[tid] = row;
    size_t rr = (size_t)(row < 0 ? 0 : row) * 256;
    ptab[tid]      = zg + rr;
    ptab[64 + tid] = zi + rr;
  }
  __syncthreads();
  ull acc[8][2];
  gemm_streamA2<16>(ptab, W1, Adup, Wbuf, acc, rbase, col0);
  epi_smem2<8, 1>(acc, b1, Hs, rbase, col0);
  gemm_smemA2<8, 8>(Hs, W2, Adup, Wbuf, acc, rbase, col0);
  epi_gmem2<8>(acc, b2, out, rows, rbase, col0, avg);
}

// mul: H = relu((zg*zi) @ W1 + b1); O = H @ W2 + b2
__global__ void __launch_bounds__(THREADS, 1) k_mul(
    const float* __restrict__ zg, const float* __restrict__ zi,
    const float* __restrict__ W1, const float* __restrict__ b1,
    const float* __restrict__ W2, const float* __restrict__ b2,
    float* __restrict__ out)
{
  int cnt = g_count[1];
  int base = blockIdx.x * 64;
  if (base >= cnt) return;
  float avg = g_avg[1];
  float* Xs   = sm;                    // 16384
  float* Hs   = sm + 16384;            // 16384
  float* Wbuf = sm + 32768;            // 16384
  ull*   Adup = (ull*)(sm + 49152);    // 2048 ull
  __shared__ int rows[64];
  TMAP();
  int rbase = rg << 3;
  if (tid < 64) {
    int i = base + tid;
    rows[tid] = (i < cnt) ? g_bucket[1 * B_ROWS + i] : -1;
  }
  __syncthreads();
  const float4* zg4 = (const float4*)zg;
  const float4* zi4 = (const float4*)zi;
  float4* Xs4 = (float4*)Xs;
  for (int i = tid; i < 64 * 64; i += THREADS) {
    int r = i >> 6, c4 = i & 63;
    int row = rows[r];
    float4 v = make_float4(0.f, 0.f, 0.f, 0.f);
    if (row >= 0) {
      float4 g = zg4[(size_t)row * 64 + c4];
      float4 z = zi4[(size_t)row * 64 + c4];
      v = make_float4(g.x * z.x, g.y * z.y, g.z * z.z, g.w * z.w);
    }
    Xs4[i] = v;
  }
  __syncthreads();
  ull acc[8][2];
  gemm_smemA2<8, 8>(Xs, W1, Adup, Wbuf, acc, rbase, col0);
  epi_smem2<8, 1>(acc, b1, Hs, rbase, col0);
  gemm_smemA2<8, 8>(Hs, W2, Adup, Wbuf, acc, rbase, col0);
  epi_gmem2<8>(acc, b2, out, rows, rbase, col0, avg);
}

// wsum: alpha = sigmoid([zg,zi] @ Wa + ba); h = alpha*zg + (1-alpha)*zi; O = h @ Wo + bo
__global__ void __launch_bounds__(THREADS, 1) k_wsum(
    const float* __restrict__ zg, const float* __restrict__ zi,
    const float* __restrict__ Wa, const float* __restrict__ ba,
    const float* __restrict__ Wo, const float* __restrict__ bo,
    float* __restrict__ out)
{
  int cnt = g_count[3];
  int base = blockIdx.x * 64;
  if (base >= cnt) return;
  float avg = g_avg[3];
  float* Hs   = sm;
  float* Wbuf = sm + 16384;
  ull*   Adup = (ull*)(sm + 32768);
  __shared__ int rows[64];
  __shared__ const float* ptab[128];
  TMAP();
  int rbase = rg << 3;
  if (tid < 64) {
    int i = base + tid;
    int row = (i < cnt) ? g_bucket[3 * B_ROWS + i] : -1;
    rows[tid] = row;
    size_t rr = (size_t)(row < 0 ? 0 : row) * 256;
    ptab[tid]      = zg + rr;
    ptab[64 + tid] = zi + rr;
  }
  __syncthreads();
  ull acc[8][2];
  gemm_streamA2<16>(ptab, Wa, Adup, Wbuf, acc, rbase, col0);
  epi_smem2<8, 2>(acc, ba, Hs, rbase, col0);   // alpha = sigmoid
  // h = alpha*zg + (1-alpha)*zi, in place
  const float4* zg4 = (const float4*)zg;
  const float4* zi4 = (const float4*)zi;
  float4* Hs4 = (float4*)Hs;
  for (int i = tid; i < 64 * 64; i += THREADS) {
    int r = i >> 6, c4 = i & 63;
    int row = rows[r];
    float4 h = make_float4(0.f, 0.f, 0.f, 0.f);
    if (row >= 0) {
      float4 a = Hs4[i];
      float4 g = zg4[(size_t)row * 64 + c4];
      float4 z = zi4[(size_t)row * 64 + c4];
      h = make_float4(a.x * g.x + (1.f - a.x) * z.x,
                      a.y * g.y + (1.f - a.y) * z.y,
                      a.z * g.z + (1.f - a.z) * z.z,
                      a.w * g.w + (1.f - a.w) * z.w);
    }
    Hs4[i] = h;
  }
  __syncthreads();
  ull acc2[8][2];
  gemm_smemA2<8, 8>(Hs, Wo, Adup, Wbuf, acc2, rbase, col0);
  epi_gmem2<8>(acc2, bo, out, rows, rbase, col0, avg);
}

// attn: QKV over 64 token rows (32 pairs), pair-softmax -> coefs, V-combine,
// then 2 chained 256x256 GEMMs on the 32 combined rows.
__global__ void __launch_bounds__(THREADS, 1) k_attn(
    const float* __restrict__ zg, const float* __restrict__ zi,
    const float* __restrict__ Wq, const float* __restrict__ bq,
    const float* __restrict__ Wk, const float* __restrict__ bk,
    const float* __restrict__ Wv, const float* __restrict__ bv,
    const float* __restrict__ Wo, const float* __restrict__ bo,
    const float* __restrict__ Wfc, const float* __restrict__ bfc,
    float* __restrict__ out)
{
  int cnt = g_count[2];
  int base = blockIdx.x * 32;
  if (base >= cnt) return;
  float avg = g_avg[2];
  float* Qs   = sm;                    // 16384 (later Ms 32x256)
  float* Ks   = sm + 16384;            // 16384 (later Os 32x256)
  float* Wbuf = sm + 32768;            // 16384
  ull*   Adup = (ull*)(sm + 49152);    // 2048 ull
  __shared__ int rows[32];
  __shared__ const float* ptab[64];
  __shared__ float Cf[32 * 8];
  TMAP();
  int rbase = rg << 3;
  if (tid < 64) {
    int pair = tid >> 1;
    int i = base + pair;
    int row = (i < cnt) ? g_bucket[2 * B_ROWS + i] : -1;
    if ((tid & 1) == 0) rows[pair] = row;
    size_t rr = (size_t)(row < 0 ? 0 : row) * 256;
    ptab[tid] = ((tid & 1) ? zi : zg) + rr;
  }
  __syncthreads();

  ull acc[8][2];
  gemm_streamA2<8>(ptab, Wq, Adup, Wbuf, acc, rbase, col0);
  epi_smem2<8, 0>(acc, bq, Qs, rbase, col0);
  gemm_streamA2<8>(ptab, Wk, Adup, Wbuf, acc, rbase, col0);
  epi_smem2<8, 0>(acc, bk, Ks, rbase, col0);

  // scores + softmax -> per-head pair coefficients. 16 warps x 2 pairs.
  {
    int warp = tid >> 5, lane = tid & 31;
    #pragma unroll
    for (int rr = 0; rr < 2; rr++) {
      int pair = warp * 2 + rr;
      #pragma unroll
      for (int h = 0; h < 4; h++) {
        float d00 = 0.f, d01 = 0.f, d10 = 0.f, d11 = 0.f;
        int cb = h * 64;
        #pragma unroll
        for (int u = 0; u < 2; u++) {
          int c = cb + lane + u * 32;
          float q0 = Qs[(2 * pair) * 256 + c], q1 = Qs[(2 * pair + 1) * 256 + c];
          float k0 = Ks[(2 * pair) * 256 + c], k1 = Ks[(2 * pair + 1) * 256 + c];
          d00 += q0 * k0; d01 += q0 * k1; d10 += q1 * k0; d11 += q1 * k1;
        }
        #pragma unroll
        for (int off = 16; off; off >>= 1) {
          d00 += __shfl_down_sync(0xffffffffu, d00, off);
          d01 += __shfl_down_sync(0xffffffffu, d01, off);
          d10 += __shfl_down_sync(0xffffffffu, d10, off);
          d11 += __shfl_down_sync(0xffffffffu, d11, off);
        }
        if (lane == 0) {
          const float s = 0.125f;  // 1/sqrt(64)
          d00 *= s; d01 *= s; d10 *= s; d11 *= s;
          float m0 = fmaxf(d00, d01), m1 = fmaxf(d10, d11);
          float e00 = expf(d00 - m0), e01 = expf(d01 - m0);
          float e10 = expf(d10 - m1), e11 = expf(d11 - m1);
          float i0 = 1.f / (e00 + e01), i1 = 1.f / (e10 + e11);
          Cf[pair * 8 + h * 2 + 0] = 0.5f * (e00 * i0 + e10 * i1);
          Cf[pair * 8 + h * 2 + 1] = 0.5f * (e01 * i0 + e11 * i1);
        }
      }
    }
  }
  __syncthreads();

  // V GEMM with pair-combine epilogue -> Ms (= Qs region)
  gemm_streamA2<8>(ptab, Wv, Adup, Wbuf, acc, rbase, col0);
  {
    float* Ms = Qs;
    float2 bv0 = *(const float2*)(bv + col0);
    float2 bv1 = *(const float2*)(bv + col0 + 64);
    #pragma unroll
    for (int q = 0; q < 4; q++) {
      int pair = rg * 4 + q;
      #pragma unroll
      for (int cp = 0; cp < 2; cp++) {
        int head = 2 * cgh + cp;
        float c0 = Cf[pair * 8 + head * 2 + 0];
        float c1 = Cf[pair * 8 + head * 2 + 1];
        float2 v0 = funpack(acc[2 * q][cp]);
        float2 v1 = funpack(acc[2 * q + 1][cp]);
        float2 b = cp ? bv1 : bv0;
        // sum of coefs == 1, so bias passes straight through
        float2 m = make_float2(c0 * v0.x + c1 * v1.x + b.x,
                               c0 * v0.y + c1 * v1.y + b.y);
        *(float2*)(Ms + pair * 256 + col0 + cp * 64) = m;
      }
    }
  }
  __syncthreads();

  // O = Ms @ Wo + bo   (32 rows, 4 rows/thread)
  int rbase4 = rg << 2;
  ull acc2[4][2];
  gemm_smemA2<4, 8>(Qs, Wo, Adup, Wbuf, acc2, rbase4, col0);
  epi_smem2<4, 0>(acc2, bo, Ks, rbase4, col0);   // Os = Ks region
  gemm_smemA2<4, 8>(Ks, Wfc, Adup, Wbuf, acc2, rbase4, col0);
  epi_gmem2<4>(acc2, bfc, out, rows, rbase4, col0, avg);
}

// ---------------- launch ---------------------------------------------------
extern "C" void kernel_launch(void* const* d_in, const int* in_sizes, int n_in,
                              void* d_out, int out_size) {
  (void)in_sizes; (void)n_in;
  const float* zg  = (const float*)d_in[0];
  const float* zi  = (const float*)d_in[1];
  const float* gW  = (const float*)d_in[2];
  const float* gb  = (const float*)d_in[3];
  const float* cW1 = (const float*)d_in[4];
  const float* cb1 = (const float*)d_in[5];
  const float* cW2 = (const float*)d_in[6];
  const float* cb2 = (const float*)d_in[7];
  const float* mW1 = (const float*)d_in[8];
  const float* mb1 = (const float*)d_in[9];
  const float* mW2 = (const float*)d_in[10];
  const float* mb2 = (const float*)d_in[11];
  const float* aWq = (const float*)d_in[12];
  const float* abq = (const float*)d_in[13];
  const float* aWk = (const float*)d_in[14];
  const float* abk = (const float*)d_in[15];
  const float* aWv = (const float*)d_in[16];
  const float* abv = (const float*)d_in[17];
  const float* aWo = (const float*)d_in[18];
  const float* abo = (const float*)d_in[19];
  const float* aWfc = (const float*)d_in[20];
  const float* abfc = (const float*)d_in[21];
  const float* wWa = (const float*)d_in[22];
  const float* wba = (const float*)d_in[23];
  const float* wWo = (const float*)d_in[24];
  const float* wbo = (const float*)d_in[25];
  float* out = (float*)d_out;

  const int SM_CONCAT = (16384 + 16384 + 4096) * 4;            // 147456
  const int SM_MUL    = (16384 + 16384 + 16384 + 4096) * 4;    // 212992
  const int SM_WSUM   = SM_CONCAT;
  const int SM_ATTN   = SM_MUL;

  cudaFuncSetAttribute(k_concat, cudaFuncAttributeMaxDynamicSharedMemorySize, SM_CONCAT);
  cudaFuncSetAttribute(k_mul,    cudaFuncAttributeMaxDynamicSharedMemorySize, SM_MUL);
  cudaFuncSetAttribute(k_wsum,   cudaFuncAttributeMaxDynamicSharedMemorySize, SM_WSUM);
  cudaFuncSetAttribute(k_attn,   cudaFuncAttributeMaxDynamicSharedMemorySize, SM_ATTN);

  k_reset<<<1, 32>>>();
  k_gate<<<B_ROWS / 8, 256>>>(zg, zi, gW, gb);
  k_finalize<<<1, 32>>>(out, out_size);
  k_concat<<<B_ROWS / 64, THREADS, SM_CONCAT>>>(zg, zi, cW1, cb1, cW2, cb2, out);
  k_mul<<<B_ROWS / 64, THREADS, SM_MUL>>>(zg, zi, mW1, mb1, mW2, mb2, out);
  k_attn<<<B_ROWS / 32, THREADS, SM_ATTN>>>(zg, zi, aWq, abq, aWk, abk, aWv, abv,
                                            aWo, abo, aWfc, abfc, out);
  k_wsum<<<B_ROWS / 64, THREADS, SM_WSUM>>>(zg, zi, wWa, wba, wWo, wbo, out);
}

// round 8
// speedup vs baseline: 1.8154x; 1.0009x over previous
#include <cuda_runtime.h>
#include <math.h>

#define B_ROWS 131072
#define NEXP   4
#define CH     16      // K-chunk size

typedef unsigned long long ull;

// ---------------- device scratch ------------------------------------------
__device__ int    g_count[NEXP];
__device__ double g_probsum[NEXP];
__device__ float  g_avg[NEXP];
__device__ int    g_bucket[NEXP * B_ROWS];

// ---------------- f32x2 helpers -------------------------------------------
__device__ __forceinline__ void ffma2(ull& d, ull a, ull b) {
  asm("fma.rn.f32x2 %0, %1, %2, %0;" : "+l"(d) : "l"(a), "l"(b));
}
__device__ __forceinline__ float2 funpack(ull v) {
  float2 f; asm("mov.b64 {%0, %1}, %2;" : "=f"(f.x), "=f"(f.y) : "l"(v)); return f;
}

// ---------------- cp.async helpers ----------------------------------------
__device__ __forceinline__ void cp16(void* sdst, const void* gsrc) {
  unsigned s = (unsigned)__cvta_generic_to_shared(sdst);
  asm volatile("cp.async.cg.shared.global [%0], [%1], 16;\n" :: "r"(s), "l"(gsrc));
}
__device__ __forceinline__ void cp_commit() {
  asm volatile("cp.async.commit_group;\n" ::: "memory");
}
__device__ __forceinline__ void cp_wait1() {
  asm volatile("cp.async.wait_group 1;\n" ::: "memory");
}

// W chunk: CH x 256 floats (16KB). 256 threads, 4 cp16 each.
__device__ __forceinline__ void stage_W(float* Wbuf, const float* Wg, int kc) {
  int t = threadIdx.x;
  const float4* src = (const float4*)(Wg + (size_t)kc * 256);
  #pragma unroll
  for (int i = 0; i < 4; i++)
    cp16(Wbuf + (i * 256 + t) * 4, src + i * 256 + t);
}

// ---------------- packed-FMA chunk ----------------------------------------
// Thread tile: NR rows x 8 cols (4 col-pairs). acc[r][cp] = f32x2 over cols
// (2*lane+64*cp, +1), row rbase+r. Adup: [rows][CH] ull of (a,a).
template<int NR>
__device__ __forceinline__ void chunk2(
    const ull* __restrict__ Adup, const float* __restrict__ Wb,
    ull (&acc)[NR][4], int rbase, int lane)
{
  #pragma unroll
  for (int k = 0; k < CH; k++) {
    ull w0 = *(const ull*)(Wb + k * 256 + 2 * lane);
    ull w1 = *(const ull*)(Wb + k * 256 + 2 * lane + 64);
    ull w2 = *(const ull*)(Wb + k * 256 + 2 * lane + 128);
    ull w3 = *(const ull*)(Wb + k * 256 + 2 * lane + 192);
    #pragma unroll
    for (int r = 0; r < NR; r++) {
      ull a = Adup[(rbase + r) * CH + k];     // warp-broadcast
      ffma2(acc[r][0], a, w0);
      ffma2(acc[r][1], a, w1);
      ffma2(acc[r][2], a, w2);
      ffma2(acc[r][3], a, w3);
    }
  }
}

// ---------------- generic GEMM core ----------------------------------------
// C(ROWS x 256) += A(ROWS x NC*CH) @ W. A fetched by functor (float4 per
// (chunk, ar, aseg)), duplicated into Adup. W double-buffered via cp.async.
template<int ROWS, int NC, class F>
__device__ __forceinline__ void gemmT(
    F fetch, const float* __restrict__ Wg,
    ull* Adup, float* Wbuf, ull (&acc)[ROWS / 8][4], int rbase, int lane)
{
  constexpr int NR = ROWS / 8;
  #pragma unroll
  for (int r = 0; r < NR; r++)
    #pragma unroll
    for (int c = 0; c < 4; c++) acc[r][c] = 0ULL;
  int t = threadIdx.x;
  int ar = t >> 2, aseg = (t & 3) * 4;
  bool act = (ar < ROWS);
  float4 av = make_float4(0.f, 0.f, 0.f, 0.f);
  if (act) av = fetch(0, ar, aseg);
  stage_W(Wbuf, Wg, 0);            cp_commit();
  stage_W(Wbuf + CH * 256, Wg, CH); cp_commit();
  #pragma unroll 1
  for (int c = 0; c < NC; c++) {
    if (act) {
      float4* d = (float4*)(Adup + ar * CH + aseg);
      d[0] = make_float4(av.x, av.x, av.y, av.y);
      d[1] = make_float4(av.z, av.z, av.w, av.w);
      if (c + 1 < NC) av = fetch(c + 1, ar, aseg);
    }
    cp_wait1(); __syncthreads();
    chunk2<NR>(Adup, Wbuf + (c & 1) * (CH * 256), acc, rbase, lane);
    __syncthreads();
    if (c + 2 < NC) stage_W(Wbuf + (c & 1) * (CH * 256), Wg, (c + 2) * CH);
    cp_commit();
  }
}

// ---------------- epilogues ------------------------------------------------
template<int NR, int ACT>
__device__ __forceinline__ void epi_smem2(
    ull (&acc)[NR][4], const float* __restrict__ bias,
    float* Cs, int rbase, int lane)
{
  #pragma unroll
  for (int cp = 0; cp < 4; cp++) {
    float2 b = *(const float2*)(bias + 2 * lane + 64 * cp);
    #pragma unroll
    for (int r = 0; r < NR; r++) {
      float2 v = funpack(acc[r][cp]);
      v.x += b.x; v.y += b.y;
      if (ACT == 1) { v.x = fmaxf(v.x, 0.f); v.y = fmaxf(v.y, 0.f); }
      if (ACT == 2) { v.x = 1.f/(1.f+expf(-v.x)); v.y = 1.f/(1.f+expf(-v.y)); }
      *(float2*)(Cs + (rbase + r) * 256 + 2 * lane + 64 * cp) = v;
    }
  }
  __syncthreads();
}

template<int NR>
__device__ __forceinline__ void epi_gmem2(
    ull (&acc)[NR][4], const float* __restrict__ bias,
    float* __restrict__ out, const int* rows, int rbase, int lane, float avg)
{
  #pragma unroll
  for (int r = 0; r < NR; r++) {
    int row = rows[rbase + r];
    if (row < 0) continue;
    #pragma unroll
    for (int cp = 0; cp < 4; cp++) {
      float2 b = *(const float2*)(bias + 2 * lane + 64 * cp);
      float2 v = funpack(acc[r][cp]);
      v.x = (v.x + b.x) * avg; v.y = (v.y + b.y) * avg;
      *(float2*)(out + (size_t)row * 256 + 2 * lane + 64 * cp) = v;
    }
  }
}

// ---------------- reset / gate / finalize ----------------------------------
__global__ void k_reset() {
  int t = threadIdx.x;
  if (t < NEXP) { g_count[t] = 0; g_probsum[t] = 0.0; }
}

__global__ void __launch_bounds__(256) k_gate(
    const float* __restrict__ zg, const float* __restrict__ zi,
    const float* __restrict__ gW, const float* __restrict__ gb)
{
  __shared__ float  sW[2048];
  __shared__ int    s_cnt[NEXP];
  __shared__ double s_psum[NEXP];
  __shared__ int    s_base[NEXP];
  int tid = threadIdx.x;
  for (int i = tid; i < 2048; i += 256) sW[i] = gW[i];
  if (tid < NEXP) { s_cnt[tid] = 0; s_psum[tid] = 0.0; }
  __syncthreads();

  int lane = tid & 31, warp = tid >> 5;
  int row  = blockIdx.x * 8 + warp;
  const float4* zg4 = (const float4*)(zg + (size_t)row * 256);
  const float4* zi4 = (const float4*)(zi + (size_t)row * 256);
  float a0 = 0.f, a1 = 0.f, a2 = 0.f, a3 = 0.f;
  float4 xs[4];
  xs[0] = zg4[lane]; xs[1] = zg4[lane + 32];
  xs[2] = zi4[lane]; xs[3] = zi4[lane + 32];
  int dbase[4] = { 4 * lane, 128 + 4 * lane, 256 + 4 * lane, 384 + 4 * lane };
  #pragma unroll
  for (int q = 0; q < 4; q++) {
    const float* xv = (const float*)&xs[q];
    #pragma unroll
    for (int j = 0; j < 4; j++) {
      float x = xv[j];
      float4 w = *(const float4*)&sW[(dbase[q] + j) * 4];
      a0 += x * w.x; a1 += x * w.y; a2 += x * w.z; a3 += x * w.w;
    }
  }
  #pragma unroll
  for (int off = 16; off; off >>= 1) {
    a0 += __shfl_down_sync(0xffffffffu, a0, off);
    a1 += __shfl_down_sync(0xffffffffu, a1, off);
    a2 += __shfl_down_sync(0xffffffffu, a2, off);
    a3 += __shfl_down_sync(0xffffffffu, a3, off);
  }
  int myE = 0, myslot = 0;
  if (lane == 0) {
    float l0 = a0 + gb[0], l1 = a1 + gb[1], l2 = a2 + gb[2], l3 = a3 + gb[3];
    float m = fmaxf(fmaxf(l0, l1), fmaxf(l2, l3));
    float s = expf(l0 - m) + expf(l1 - m) + expf(l2 - m) + expf(l3 - m);
    int best = 0; float bl = l0;
    if (l1 > bl) { bl = l1; best = 1; }
    if (l2 > bl) { bl = l2; best = 2; }
    if (l3 > bl) { bl = l3; best = 3; }
    float p = expf(bl - m) / s;
    myslot = atomicAdd(&s_cnt[best], 1);
    atomicAdd(&s_psum[best], (double)p);
    myE = best;
  }
  __syncthreads();
  if (tid < NEXP) {
    s_base[tid] = atomicAdd(&g_count[tid], s_cnt[tid]);
    atomicAdd(&g_probsum[tid], s_psum[tid]);
  }
  __syncthreads();
  if (lane == 0) g_bucket[myE * B_ROWS + s_base[myE] + myslot] = row;
}

__global__ void k_finalize(float* out, int out_size) {
  int t = threadIdx.x;
  if (t < NEXP) {
    int c = g_count[t];
    g_avg[t] = (c > 0) ? (float)(g_probsum[t] / (double)c) : 0.f;
  }
  __syncthreads();
  if (t == 0) {
    float aux = 0.f;
    #pragma unroll
    for (int e = 0; e < NEXP; e++) {
      float u = (float)g_count[e] / (float)B_ROWS;
      aux += u * u;
    }
    aux *= (float)NEXP;
    if (out_size > B_ROWS * 256) out[(size_t)B_ROWS * 256] = aux;
  }
}

// ---------------- expert kernels -------------------------------------------
extern __shared__ float sm[];

// smem layout (floats): Hs/Qs [0,16384) | Wbuf [16384, 24576) | Adup [24576, 26624)
#define SMF_HS    0
#define SMF_WBUF  16384
#define SMF_ADUP  24576

// concat: H = relu([zg,zi] @ W1 + b1); O = H @ W2 + b2. 64-row tiles.
__global__ void __launch_bounds__(256, 2) k_concat(
    const float* __restrict__ zg, const float* __restrict__ zi,
    const float* __restrict__ W1, const float* __restrict__ b1,
    const float* __restrict__ W2, const float* __restrict__ b2,
    float* __restrict__ out)
{
  int cnt = g_count[0];
  int base = blockIdx.x * 64;
  if (base >= cnt) return;
  float avg = g_avg[0];
  float* Hs   = sm + SMF_HS;
  float* Wbuf = sm + SMF_WBUF;
  ull*   Adup = (ull*)(sm + SMF_ADUP);
  __shared__ int rows[64];
  __shared__ const float* ptab[128];
  int tid = threadIdx.x;
  int lane = tid & 31, rbase = (tid >> 5) * 8;
  if (tid < 64) {
    int i = base + tid;
    int row = (i < cnt) ? g_bucket[0 * B_ROWS + i] : -1;
    rows[tid] = row;
    size_t rr = (size_t)(row < 0 ? 0 : row) * 256;
    ptab[tid]      = zg + rr;
    ptab[64 + tid] = zi + rr;
  }
  __syncthreads();
  auto fetchCat = [&](int c, int ar, int aseg) -> float4 {
    int kc = c * CH;
    return *(const float4*)(ptab[((kc >> 8) << 6) + ar] + (kc & 255) + aseg);
  };
  auto fetchH = [&](int c, int ar, int aseg) -> float4 {
    return *(const float4*)(Hs + ar * 256 + c * CH + aseg);
  };
  ull acc[8][4];
  gemmT<64, 32>(fetchCat, W1, Adup, Wbuf, acc, rbase, lane);
  epi_smem2<8, 1>(acc, b1, Hs, rbase, lane);
  gemmT<64, 16>(fetchH, W2, Adup, Wbuf, acc, rbase, lane);
  epi_gmem2<8>(acc, b2, out, rows, rbase, lane, avg);
}

// mul: H = relu((zg*zi) @ W1 + b1); O = H @ W2 + b2. A streamed (no Xs).
__global__ void __launch_bounds__(256, 2) k_mul(
    const float* __restrict__ zg, const float* __restrict__ zi,
    const float* __restrict__ W1, const float* __restrict__ b1,
    const float* __restrict__ W2, const float* __restrict__ b2,
    float* __restrict__ out)
{
  int cnt = g_count[1];
  int base = blockIdx.x * 64;
  if (base >= cnt) return;
  float avg = g_avg[1];
  float* Hs   = sm + SMF_HS;
  float* Wbuf = sm + SMF_WBUF;
  ull*   Adup = (ull*)(sm + SMF_ADUP);
  __shared__ int rows[64];
  __shared__ const float* ptab[128];
  int tid = threadIdx.x;
  int lane = tid & 31, rbase = (tid >> 5) * 8;
  if (tid < 64) {
    int i = base + tid;
    int row = (i < cnt) ? g_bucket[1 * B_ROWS + i] : -1;
    rows[tid] = row;
    size_t rr = (size_t)(row < 0 ? 0 : row) * 256;
    ptab[tid]      = zg + rr;
    ptab[64 + tid] = zi + rr;
  }
  __syncthreads();
  auto fetchM = [&](int c, int ar, int aseg) -> float4 {
    int kc = c * CH;
    float4 g = *(const float4*)(ptab[ar] + kc + aseg);
    float4 z = *(const float4*)(ptab[64 + ar] + kc + aseg);
    return make_float4(g.x * z.x, g.y * z.y, g.z * z.z, g.w * z.w);
  };
  auto fetchH = [&](int c, int ar, int aseg) -> float4 {
    return *(const float4*)(Hs + ar * 256 + c * CH + aseg);
  };
  ull acc[8][4];
  gemmT<64, 16>(fetchM, W1, Adup, Wbuf, acc, rbase, lane);
  epi_smem2<8, 1>(acc, b1, Hs, rbase, lane);
  gemmT<64, 16>(fetchH, W2, Adup, Wbuf, acc, rbase, lane);
  epi_gmem2<8>(acc, b2, out, rows, rbase, lane, avg);
}

// wsum: alpha = sigmoid([zg,zi] @ Wa + ba); h = alpha*zg + (1-alpha)*zi (streamed);
// O = h @ Wo + bo
__global__ void __launch_bounds__(256, 2) k_wsum(
    const float* __restrict__ zg, const float* __restrict__ zi,
    const float* __restrict__ Wa, const float* __restrict__ ba,
    const float* __restrict__ Wo, const float* __restrict__ bo,
    float* __restrict__ out)
{
  int cnt = g_count[3];
  int base = blockIdx.x * 64;
  if (base >= cnt) return;
  float avg = g_avg[3];
  float* Hs   = sm + SMF_HS;       // alpha
  float* Wbuf = sm + SMF_WBUF;
  ull*   Adup = (ull*)(sm + SMF_ADUP);
  __shared__ int rows[64];
  __shared__ const float* ptab[128];
  int tid = threadIdx.x;
  int lane = tid & 31, rbase = (tid >> 5) * 8;
  if (tid < 64) {
    int i = base + tid;
    int row = (i < cnt) ? g_bucket[3 * B_ROWS + i] : -1;
    rows[tid] = row;
    size_t rr = (size_t)(row < 0 ? 0 : row) * 256;
    ptab[tid]      = zg + rr;
    ptab[64 + tid] = zi + rr;
  }
  __syncthreads();
  auto fetchCat = [&](int c, int ar, int aseg) -> float4 {
    int kc = c * CH;
    return *(const float4*)(ptab[((kc >> 8) << 6) + ar] + (kc & 255) + aseg);
  };
  auto fetchHW = [&](int c, int ar, int aseg) -> float4 {
    int kc = c * CH;
    float4 a = *(const float4*)(Hs + ar * 256 + kc + aseg);
    float4 g = *(const float4*)(ptab[ar] + kc + aseg);
    float4 z = *(const float4*)(ptab[64 + ar] + kc + aseg);
    return make_float4(a.x * g.x + (1.f - a.x) * z.x,
                       a.y * g.y + (1.f - a.y) * z.y,
                       a.z * g.z + (1.f - a.z) * z.z,
                       a.w * g.w + (1.f - a.w) * z.w);
  };
  ull acc[8][4];
  gemmT<64, 32>(fetchCat, Wa, Adup, Wbuf, acc, rbase, lane);
  epi_smem2<8, 2>(acc, ba, Hs, rbase, lane);   // alpha = sigmoid
  gemmT<64, 16>(fetchHW, Wo, Adup, Wbuf, acc, rbase, lane);
  epi_gmem2<8>(acc, bo, out, rows, rbase, lane, avg);
}

// attn: 16 pairs (32 token rows) per block. QKV GEMMs -> pair softmax coefs
// -> V combine -> 2 chained 256x256 GEMMs on 16 combined rows.
__global__ void __launch_bounds__(256, 2) k_attn(
    const float* __restrict__ zg, const float* __restrict__ zi,
    const float* __restrict__ Wq, const float* __restrict__ bq,
    const float* __restrict__ Wk, const float* __restrict__ bk,
    const float* __restrict__ Wv, const float* __restrict__ bv,
    const float* __restrict__ Wo, const float* __restrict__ bo,
    const float* __restrict__ Wfc, const float* __restrict__ bfc,
    float* __restrict__ out)
{
  int cnt = g_count[2];
  int base = blockIdx.x * 16;
  if (base >= cnt) return;
  float avg = g_avg[2];
  float* Qs   = sm;                 // 8192 (32x256) ; later Ms (16x256)
  float* Ks   = sm + 8192;          // 8192 (32x256) ; later Os (16x256)
  float* Wbuf = sm + 16384;         // 8192
  ull*   Adup = (ull*)(sm + 24576); // 512 ull
  __shared__ int rows[16];
  __shared__ const float* ptab[32];
  __shared__ float Cf[16 * 8];
  int tid = threadIdx.x;
  int lane = tid & 31, rg = tid >> 5;
  int rbase = rg * 4;               // ROWS=32 phase
  if (tid < 32) {
    int pair = tid >> 1;
    int i = base + pair;
    int row = (i < cnt) ? g_bucket[2 * B_ROWS + i] : -1;
    if ((tid & 1) == 0) rows[pair] = row;
    size_t rr = (size_t)(row < 0 ? 0 : row) * 256;
    ptab[tid] = ((tid & 1) ? zi : zg) + rr;
  }
  __syncthreads();

  auto fetchT = [&](int c, int ar, int aseg) -> float4 {
    return *(const float4*)(ptab[ar] + c * CH + aseg);
  };

  ull acc[4][4];
  gemmT<32, 16>(fetchT, Wq, Adup, Wbuf, acc, rbase, lane);
  epi_smem2<4, 0>(acc, bq, Qs, rbase, lane);
  gemmT<32, 16>(fetchT, Wk, Adup, Wbuf, acc, rbase, lane);
  epi_smem2<4, 0>(acc, bk, Ks, rbase, lane);

  // scores + softmax -> per-head pair coefficients. 8 warps x 2 pairs.
  {
    #pragma unroll
    for (int rr = 0; rr < 2; rr++) {
      int pair = rg * 2 + rr;
      #pragma unroll
      for (int h = 0; h < 4; h++) {
        float d00 = 0.f, d01 = 0.f, d10 = 0.f, d11 = 0.f;
        int cb = h * 64;
        #pragma unroll
        for (int u = 0; u < 2; u++) {
          int c = cb + lane + u * 32;
          float q0 = Qs[(2 * pair) * 256 + c], q1 = Qs[(2 * pair + 1) * 256 + c];
          float k0 = Ks[(2 * pair) * 256 + c], k1 = Ks[(2 * pair + 1) * 256 + c];
          d00 += q0 * k0; d01 += q0 * k1; d10 += q1 * k0; d11 += q1 * k1;
        }
        #pragma unroll
        for (int off = 16; off; off >>= 1) {
          d00 += __shfl_down_sync(0xffffffffu, d00, off);
          d01 += __shfl_down_sync(0xffffffffu, d01, off);
          d10 += __shfl_down_sync(0xffffffffu, d10, off);
          d11 += __shfl_down_sync(0xffffffffu, d11, off);
        }
        if (lane == 0) {
          const float s = 0.125f;  // 1/sqrt(64)
          d00 *= s; d01 *= s; d10 *= s; d11 *= s;
          float m0 = fmaxf(d00, d01), m1 = fmaxf(d10, d11);
          float e00 = expf(d00 - m0), e01 = expf(d01 - m0);
          float e10 = expf(d10 - m1), e11 = expf(d11 - m1);
          float i0 = 1.f / (e00 + e01), i1 = 1.f / (e10 + e11);
          Cf[pair * 8 + h * 2 + 0] = 0.5f * (e00 * i0 + e10 * i1);
          Cf[pair * 8 + h * 2 + 1] = 0.5f * (e01 * i0 + e11 * i1);
        }
      }
    }
  }
  __syncthreads();

  // V GEMM; combine pairs in epilogue -> Ms (reuses Qs region)
  gemmT<32, 16>(fetchT, Wv, Adup, Wbuf, acc, rbase, lane);
  {
    float* Ms = Qs;
    #pragma unroll
    for (int q = 0; q < 2; q++) {
      int pair = rg * 2 + q;
      #pragma unroll
      for (int cp = 0; cp < 4; cp++) {
        // head of cols 2*lane+64*cp (+1): 2*lane<64 -> head == cp
        float c0 = Cf[pair * 8 + cp * 2 + 0];
        float c1 = Cf[pair * 8 + cp * 2 + 1];
        float2 v0 = funpack(acc[2 * q][cp]);
        float2 v1 = funpack(acc[2 * q + 1][cp]);
        float2 b = *(const float2*)(bv + 2 * lane + 64 * cp);
        // coefs sum to 1 -> bias passes through
        float2 m = make_float2(c0 * v0.x + c1 * v1.x + b.x,
                               c0 * v0.y + c1 * v1.y + b.y);
        *(float2*)(Ms + pair * 256 + 2 * lane + 64 * cp) = m;
      }
    }
  }
  __syncthreads();

  // O = Ms @ Wo + bo; final = Os @ Wfc + bfc  (16 rows, NR=2)
  auto fetchMs = [&](int c, int ar, int aseg) -> float4 {
    return *(const float4*)(Qs + ar * 256 + c * CH + aseg);
  };
  auto fetchOs = [&](int c, int ar, int aseg) -> float4 {
    return *(const float4*)(Ks + ar * 256 + c * CH + aseg);
  };
  int rbase2 = rg * 2;
  ull acc2[2][4];
  gemmT<16, 16>(fetchMs, Wo, Adup, Wbuf, acc2, rbase2, lane);
  epi_smem2<2, 0>(acc2, bo, Ks, rbase2, lane);
  gemmT<16, 16>(fetchOs, Wfc, Adup, Wbuf, acc2, rbase2, lane);
  epi_gmem2<2>(acc2, bfc, out, rows, rbase2, lane, avg);
}

// ---------------- launch ---------------------------------------------------
extern "C" void kernel_launch(void* const* d_in, const int* in_sizes, int n_in,
                              void* d_out, int out_size) {
  (void)in_sizes; (void)n_in;
  const float* zg  = (const float*)d_in[0];
  const float* zi  = (const float*)d_in[1];
  const float* gW  = (const float*)d_in[2];
  const float* gb  = (const float*)d_in[3];
  const float* cW1 = (const float*)d_in[4];
  const float* cb1 = (const float*)d_in[5];
  const float* cW2 = (const float*)d_in[6];
  const float* cb2 = (const float*)d_in[7];
  const float* mW1 = (const float*)d_in[8];
  const float* mb1 = (const float*)d_in[9];
  const float* mW2 = (const float*)d_in[10];
  const float* mb2 = (const float*)d_in[11];
  const float* aWq = (const float*)d_in[12];
  const float* abq = (const float*)d_in[13];
  const float* aWk = (const float*)d_in[14];
  const float* abk = (const float*)d_in[15];
  const float* aWv = (const float*)d_in[16];
  const float* abv = (const float*)d_in[17];
  const float* aWo = (const float*)d_in[18];
  const float* abo = (const float*)d_in[19];
  const float* aWfc = (const float*)d_in[20];
  const float* abfc = (const float*)d_in[21];
  const float* wWa = (const float*)d_in[22];
  const float* wba = (const float*)d_in[23];
  const float* wWo = (const float*)d_in[24];
  const float* wbo = (const float*)d_in[25];
  float* out = (float*)d_out;

  const int SM_EXP  = (16384 + 8192 + 2048) * 4;   // 106496 B
  const int SM_ATTN = (8192 + 8192 + 8192 + 1024) * 4;  // 102400 B

  cudaFuncSetAttribute(k_concat, cudaFuncAttributeMaxDynamicSharedMemorySize, SM_EXP);
  cudaFuncSetAttribute(k_mul,    cudaFuncAttributeMaxDynamicSharedMemorySize, SM_EXP);
  cudaFuncSetAttribute(k_wsum,   cudaFuncAttributeMaxDynamicSharedMemorySize, SM_EXP);
  cudaFuncSetAttribute(k_attn,   cudaFuncAttributeMaxDynamicSharedMemorySize, SM_ATTN);

  k_reset<<<1, 32>>>();
  k_gate<<<B_ROWS / 8, 256>>>(zg, zi, gW, gb);
  k_finalize<<<1, 32>>>(out, out_size);
  k_concat<<<B_ROWS / 64, 256, SM_EXP>>>(zg, zi, cW1, cb1, cW2, cb2, out);
  k_mul<<<B_ROWS / 64, 256, SM_EXP>>>(zg, zi, mW1, mb1, mW2, mb2, out);
  k_attn<<<B_ROWS / 16, 256, SM_ATTN>>>(zg, zi, aWq, abq, aWk, abk, aWv, abv,
                                        aWo, abo, aWfc, abfc, out);
  k_wsum<<<B_ROWS / 64, 256, SM_EXP>>>(zg, zi, wWa, wba, wWo, wbo, out);
}

// round 9
// speedup vs baseline: 1.9821x; 1.0918x over previous
#include <cuda_runtime.h>
#include <math.h>

#define B_ROWS 131072
#define NEXP   4
#define CH     16      // K-chunk size

typedef unsigned long long ull;

// ---------------- device scratch ------------------------------------------
__device__ int    g_count[NEXP];
__device__ double g_probsum[NEXP];
__device__ float  g_avg[NEXP];
__device__ int    g_bucket[NEXP * B_ROWS];

// ---------------- f32x2 helpers -------------------------------------------
__device__ __forceinline__ void ffma2(ull& d, ull a, ull b) {
  asm("fma.rn.f32x2 %0, %1, %2, %0;" : "+l"(d) : "l"(a), "l"(b));
}
__device__ __forceinline__ float2 funpack(ull v) {
  float2 f; asm("mov.b64 {%0, %1}, %2;" : "=f"(f.x), "=f"(f.y) : "l"(v)); return f;
}

// ---------------- cp.async helpers ----------------------------------------
__device__ __forceinline__ void cp16(void* sdst, const void* gsrc) {
  unsigned s = (unsigned)__cvta_generic_to_shared(sdst);
  asm volatile("cp.async.cg.shared.global [%0], [%1], 16;\n" :: "r"(s), "l"(gsrc));
}
__device__ __forceinline__ void cp_commit() {
  asm volatile("cp.async.commit_group;\n" ::: "memory");
}
__device__ __forceinline__ void cp_wait1() {
  asm volatile("cp.async.wait_group 1;\n" ::: "memory");
}

// W chunk: CH x 256 floats (16KB). 256 threads, 4 cp16 each.
__device__ __forceinline__ void stage_W(float* Wbuf, const float* Wg, int kc) {
  int t = threadIdx.x;
  const float4* src = (const float4*)(Wg + (size_t)kc * 256);
  #pragma unroll
  for (int i = 0; i < 4; i++)
    cp16(Wbuf + (i * 256 + t) * 4, src + i * 256 + t);
}

// ---------------- packed-FMA chunk ----------------------------------------
// Thread tile: NR rows x 8 cols. Col pairs: (4L,4L+1),(4L+2,4L+3),
// (4L+128,4L+129),(4L+130,4L+131), L=lane. W via 2x LDS.128 per k.
template<int NR>
__device__ __forceinline__ void chunk2(
    const ull* __restrict__ Adup, const float* __restrict__ Wb,
    ull (&acc)[NR][4], int rbase, int lane)
{
  #pragma unroll
  for (int k = 0; k < CH; k++) {
    ulonglong2 wlo = *(const ulonglong2*)(Wb + k * 256 + 4 * lane);
    ulonglong2 whi = *(const ulonglong2*)(Wb + k * 256 + 4 * lane + 128);
    #pragma unroll
    for (int r = 0; r < NR; r++) {
      ull a = Adup[(rbase + r) * CH + k];     // warp-broadcast
      ffma2(acc[r][0], a, wlo.x);
      ffma2(acc[r][1], a, wlo.y);
      ffma2(acc[r][2], a, whi.x);
      ffma2(acc[r][3], a, whi.y);
    }
  }
}

// ---------------- generic GEMM core ----------------------------------------
template<int ROWS, int NC, class F>
__device__ __forceinline__ void gemmT(
    F fetch, const float* __restrict__ Wg,
    ull* Adup, float* Wbuf, ull (&acc)[ROWS / 8][4], int rbase, int lane)
{
  constexpr int NR = ROWS / 8;
  #pragma unroll
  for (int r = 0; r < NR; r++)
    #pragma unroll
    for (int c = 0; c < 4; c++) acc[r][c] = 0ULL;
  int t = threadIdx.x;
  int ar = t >> 2, aseg = (t & 3) * 4;
  bool act = (ar < ROWS);
  float4 av = make_float4(0.f, 0.f, 0.f, 0.f);
  if (act) av = fetch(0, ar, aseg);
  stage_W(Wbuf, Wg, 0);             cp_commit();
  stage_W(Wbuf + CH * 256, Wg, CH); cp_commit();
  #pragma unroll 1
  for (int c = 0; c < NC; c++) {
    if (act) {
      float4* d = (float4*)(Adup + ar * CH + aseg);
      d[0] = make_float4(av.x, av.x, av.y, av.y);
      d[1] = make_float4(av.z, av.z, av.w, av.w);
      if (c + 1 < NC) av = fetch(c + 1, ar, aseg);
    }
    cp_wait1(); __syncthreads();
    chunk2<NR>(Adup, Wbuf + (c & 1) * (CH * 256), acc, rbase, lane);
    __syncthreads();
    if (c + 2 < NC) stage_W(Wbuf + (c & 1) * (CH * 256), Wg, (c + 2) * CH);
    cp_commit();
  }
}

// ---------------- epilogues ------------------------------------------------
template<int NR, int ACT>
__device__ __forceinline__ void epi_smem2(
    ull (&acc)[NR][4], const float* __restrict__ bias,
    float* Cs, int rbase, int lane)
{
  float4 blo = *(const float4*)(bias + 4 * lane);
  float4 bhi = *(const float4*)(bias + 4 * lane + 128);
  #pragma unroll
  for (int r = 0; r < NR; r++) {
    float2 v0 = funpack(acc[r][0]), v1 = funpack(acc[r][1]);
    float2 v2 = funpack(acc[r][2]), v3 = funpack(acc[r][3]);
    float4 lo = make_float4(v0.x + blo.x, v0.y + blo.y, v1.x + blo.z, v1.y + blo.w);
    float4 hi = make_float4(v2.x + bhi.x, v2.y + bhi.y, v3.x + bhi.z, v3.y + bhi.w);
    if (ACT == 1) {
      lo.x = fmaxf(lo.x, 0.f); lo.y = fmaxf(lo.y, 0.f); lo.z = fmaxf(lo.z, 0.f); lo.w = fmaxf(lo.w, 0.f);
      hi.x = fmaxf(hi.x, 0.f); hi.y = fmaxf(hi.y, 0.f); hi.z = fmaxf(hi.z, 0.f); hi.w = fmaxf(hi.w, 0.f);
    }
    if (ACT == 2) {
      lo.x = 1.f/(1.f+expf(-lo.x)); lo.y = 1.f/(1.f+expf(-lo.y));
      lo.z = 1.f/(1.f+expf(-lo.z)); lo.w = 1.f/(1.f+expf(-lo.w));
      hi.x = 1.f/(1.f+expf(-hi.x)); hi.y = 1.f/(1.f+expf(-hi.y));
      hi.z = 1.f/(1.f+expf(-hi.z)); hi.w = 1.f/(1.f+expf(-hi.w));
    }
    *(float4*)(Cs + (rbase + r) * 256 + 4 * lane) = lo;
    *(float4*)(Cs + (rbase + r) * 256 + 4 * lane + 128) = hi;
  }
  __syncthreads();
}

template<int NR>
__device__ __forceinline__ void epi_gmem2(
    ull (&acc)[NR][4], const float* __restrict__ bias,
    float* __restrict__ out, const int* rows, int rbase, int lane, float avg)
{
  float4 blo = *(const float4*)(bias + 4 * lane);
  float4 bhi = *(const float4*)(bias + 4 * lane + 128);
  #pragma unroll
  for (int r = 0; r < NR; r++) {
    int row = rows[rbase + r];
    if (row < 0) continue;
    float2 v0 = funpack(acc[r][0]), v1 = funpack(acc[r][1]);
    float2 v2 = funpack(acc[r][2]), v3 = funpack(acc[r][3]);
    float4 lo = make_float4((v0.x + blo.x) * avg, (v0.y + blo.y) * avg,
                            (v1.x + blo.z) * avg, (v1.y + blo.w) * avg);
    float4 hi = make_float4((v2.x + bhi.x) * avg, (v2.y + bhi.y) * avg,
                            (v3.x + bhi.z) * avg, (v3.y + bhi.w) * avg);
    *(float4*)(out + (size_t)row * 256 + 4 * lane) = lo;
    *(float4*)(out + (size_t)row * 256 + 4 * lane + 128) = hi;
  }
}

// ---------------- reset / gate / finalize ----------------------------------
__global__ void k_reset() {
  int t = threadIdx.x;
  if (t < NEXP) { g_count[t] = 0; g_probsum[t] = 0.0; }
}

__global__ void __launch_bounds__(256) k_gate(
    const float* __restrict__ zg, const float* __restrict__ zi,
    const float* __restrict__ gW, const float* __restrict__ gb)
{
  __shared__ float  sW[2048];
  __shared__ int    s_cnt[NEXP];
  __shared__ double s_psum[NEXP];
  __shared__ int    s_base[NEXP];
  int tid = threadIdx.x;
  for (int i = tid; i < 2048; i += 256) sW[i] = gW[i];
  if (tid < NEXP) { s_cnt[tid] = 0; s_psum[tid] = 0.0; }
  __syncthreads();

  int lane = tid & 31, warp = tid >> 5;
  int row  = blockIdx.x * 8 + warp;
  const float4* zg4 = (const float4*)(zg + (size_t)row * 256);
  const float4* zi4 = (const float4*)(zi + (size_t)row * 256);
  float a0 = 0.f, a1 = 0.f, a2 = 0.f, a3 = 0.f;
  float4 xs[4];
  xs[0] = zg4[lane]; xs[1] = zg4[lane + 32];
  xs[2] = zi4[lane]; xs[3] = zi4[lane + 32];
  int dbase[4] = { 4 * lane, 128 + 4 * lane, 256 + 4 * lane, 384 + 4 * lane };
  #pragma unroll
  for (int q = 0; q < 4; q++) {
    const float* xv = (const float*)&xs[q];
    #pragma unroll
    for (int j = 0; j < 4; j++) {
      float x = xv[j];
      float4 w = *(const float4*)&sW[(dbase[q] + j) * 4];
      a0 += x * w.x; a1 += x * w.y; a2 += x * w.z; a3 += x * w.w;
    }
  }
  #pragma unroll
  for (int off = 16; off; off >>= 1) {
    a0 += __shfl_down_sync(0xffffffffu, a0, off);
    a1 += __shfl_down_sync(0xffffffffu, a1, off);
    a2 += __shfl_down_sync(0xffffffffu, a2, off);
    a3 += __shfl_down_sync(0xffffffffu, a3, off);
  }
  int myE = 0, myslot = 0;
  if (lane == 0) {
    float l0 = a0 + gb[0], l1 = a1 + gb[1], l2 = a2 + gb[2], l3 = a3 + gb[3];
    float m = fmaxf(fmaxf(l0, l1), fmaxf(l2, l3));
    float s = expf(l0 - m) + expf(l1 - m) + expf(l2 - m) + expf(l3 - m);
    int best = 0; float bl = l0;
    if (l1 > bl) { bl = l1; best = 1; }
    if (l2 > bl) { bl = l2; best = 2; }
    if (l3 > bl) { bl = l3; best = 3; }
    float p = expf(bl - m) / s;
    myslot = atomicAdd(&s_cnt[best], 1);
    atomicAdd(&s_psum[best], (double)p);
    myE = best;
  }
  __syncthreads();
  if (tid < NEXP) {
    s_base[tid] = atomicAdd(&g_count[tid], s_cnt[tid]);
    atomicAdd(&g_probsum[tid], s_psum[tid]);
  }
  __syncthreads();
  if (lane == 0) g_bucket[myE * B_ROWS + s_base[myE] + myslot] = row;
}

__global__ void k_finalize(float* out, int out_size) {
  int t = threadIdx.x;
  if (t < NEXP) {
    int c = g_count[t];
    g_avg[t] = (c > 0) ? (float)(g_probsum[t] / (double)c) : 0.f;
  }
  __syncthreads();
  if (t == 0) {
    float aux = 0.f;
    #pragma unroll
    for (int e = 0; e < NEXP; e++) {
      float u = (float)g_count[e] / (float)B_ROWS;
      aux += u * u;
    }
    aux *= (float)NEXP;
    if (out_size > B_ROWS * 256) out[(size_t)B_ROWS * 256] = aux;
  }
}

// ---------------- expert bodies --------------------------------------------
extern __shared__ float sm[];
#define SMF_HS    0
#define SMF_WBUF  16384
#define SMF_ADUP  24576

// generic 2-layer MLP expert (concat / mul / wsum variants)
template<int MODE>   // 0=concat, 1=mul, 2=wsum
__device__ __forceinline__ void mlp_body(
    int bid, int eid,
    const float* __restrict__ zg, const float* __restrict__ zi,
    const float* __restrict__ W1, const float* __restrict__ b1,
    const float* __restrict__ W2, const float* __restrict__ b2,
    float* __restrict__ out)
{
  int cnt = g_count[eid];
  int base = bid * 64;
  if (base >= cnt) return;
  float avg = g_avg[eid];
  float* Hs   = sm + SMF_HS;
  float* Wbuf = sm + SMF_WBUF;
  ull*   Adup = (ull*)(sm + SMF_ADUP);
  __shared__ int rows_m[64];
  __shared__ const float* ptab_m[128];
  int tid = threadIdx.x;
  int lane = tid & 31, rbase = (tid >> 5) * 8;
  if (tid < 64) {
    int i = base + tid;
    int row = (i < cnt) ? g_bucket[eid * B_ROWS + i] : -1;
    rows_m[tid] = row;
    size_t rr = (size_t)(row < 0 ? 0 : row) * 256;
    ptab_m[tid]      = zg + rr;
    ptab_m[64 + tid] = zi + rr;
  }
  __syncthreads();
  auto fetchCat = [&](int c, int ar, int aseg) -> float4 {
    int kc = c * CH;
    return *(const float4*)(ptab_m[((kc >> 8) << 6) + ar] + (kc & 255) + aseg);
  };
  auto fetchMul = [&](int c, int ar, int aseg) -> float4 {
    int kc = c * CH;
    float4 g = *(const float4*)(ptab_m[ar] + kc + aseg);
    float4 z = *(const float4*)(ptab_m[64 + ar] + kc + aseg);
    return make_float4(g.x * z.x, g.y * z.y, g.z * z.z, g.w * z.w);
  };
  auto fetchH = [&](int c, int ar, int aseg) -> float4 {
    return *(const float4*)(Hs + ar * 256 + c * CH + aseg);
  };
  auto fetchHW = [&](int c, int ar, int aseg) -> float4 {
    int kc = c * CH;
    float4 a = *(const float4*)(Hs + ar * 256 + kc + aseg);
    float4 g = *(const float4*)(ptab_m[ar] + kc + aseg);
    float4 z = *(const float4*)(ptab_m[64 + ar] + kc + aseg);
    return make_float4(a.x * g.x + (1.f - a.x) * z.x,
                       a.y * g.y + (1.f - a.y) * z.y,
                       a.z * g.z + (1.f - a.z) * z.z,
                       a.w * g.w + (1.f - a.w) * z.w);
  };
  ull acc[8][4];
  if (MODE == 0) {
    gemmT<64, 32>(fetchCat, W1, Adup, Wbuf, acc, rbase, lane);
    epi_smem2<8, 1>(acc, b1, Hs, rbase, lane);
    gemmT<64, 16>(fetchH, W2, Adup, Wbuf, acc, rbase, lane);
  } else if (MODE == 1) {
    gemmT<64, 16>(fetchMul, W1, Adup, Wbuf, acc, rbase, lane);
    epi_smem2<8, 1>(acc, b1, Hs, rbase, lane);
    gemmT<64, 16>(fetchH, W2, Adup, Wbuf, acc, rbase, lane);
  } else {
    gemmT<64, 32>(fetchCat, W1, Adup, Wbuf, acc, rbase, lane);
    epi_smem2<8, 2>(acc, b1, Hs, rbase, lane);   // alpha = sigmoid
    gemmT<64, 16>(fetchHW, W2, Adup, Wbuf, acc, rbase, lane);
  }
  epi_gmem2<8>(acc, b2, out, rows_m, rbase, lane, avg);
}

__device__ __forceinline__ void attn_body(
    int bid,
    const float* __restrict__ zg, const float* __restrict__ zi,
    const float* __restrict__ Wq, const float* __restrict__ bq,
    const float* __restrict__ Wk, const float* __restrict__ bk,
    const float* __restrict__ Wv, const float* __restrict__ bv,
    const float* __restrict__ Wo, const float* __restrict__ bo,
    const float* __restrict__ Wfc, const float* __restrict__ bfc,
    float* __restrict__ out)
{
  int cnt = g_count[2];
  int base = bid * 16;
  if (base >= cnt) return;
  float avg = g_avg[2];
  float* Qs   = sm;                 // 8192 (32x256); later Ms (16x256)
  float* Ks   = sm + 8192;          // 8192 (32x256); later Os (16x256)
  float* Wbuf = sm + 16384;         // 8192
  ull*   Adup = (ull*)(sm + 24576); // 512 ull
  __shared__ int rows_a[16];
  __shared__ const float* ptab_a[32];
  __shared__ float Cf[16 * 8];
  int tid = threadIdx.x;
  int lane = tid & 31, rg = tid >> 5;
  int rbase = rg * 4;
  if (tid < 32) {
    int pair = tid >> 1;
    int i = base + pair;
    int row = (i < cnt) ? g_bucket[2 * B_ROWS + i] : -1;
    if ((tid & 1) == 0) rows_a[pair] = row;
    size_t rr = (size_t)(row < 0 ? 0 : row) * 256;
    ptab_a[tid] = ((tid & 1) ? zi : zg) + rr;
  }
  __syncthreads();

  auto fetchT = [&](int c, int ar, int aseg) -> float4 {
    return *(const float4*)(ptab_a[ar] + c * CH + aseg);
  };

  ull acc[4][4];
  gemmT<32, 16>(fetchT, Wq, Adup, Wbuf, acc, rbase, lane);
  epi_smem2<4, 0>(acc, bq, Qs, rbase, lane);
  gemmT<32, 16>(fetchT, Wk, Adup, Wbuf, acc, rbase, lane);
  epi_smem2<4, 0>(acc, bk, Ks, rbase, lane);

  // scores + softmax -> per-head pair coefficients. 8 warps x 2 pairs.
  {
    #pragma unroll
    for (int rr = 0; rr < 2; rr++) {
      int pair = rg * 2 + rr;
      #pragma unroll
      for (int h = 0; h < 4; h++) {
        float d00 = 0.f, d01 = 0.f, d10 = 0.f, d11 = 0.f;
        int cb = h * 64;
        #pragma unroll
        for (int u = 0; u < 2; u++) {
          int c = cb + lane + u * 32;
          float q0 = Qs[(2 * pair) * 256 + c], q1 = Qs[(2 * pair + 1) * 256 + c];
          float k0 = Ks[(2 * pair) * 256 + c], k1 = Ks[(2 * pair + 1) * 256 + c];
          d00 += q0 * k0; d01 += q0 * k1; d10 += q1 * k0; d11 += q1 * k1;
        }
        #pragma unroll
        for (int off = 16; off; off >>= 1) {
          d00 += __shfl_down_sync(0xffffffffu, d00, off);
          d01 += __shfl_down_sync(0xffffffffu, d01, off);
          d10 += __shfl_down_sync(0xffffffffu, d10, off);
          d11 += __shfl_down_sync(0xffffffffu, d11, off);
        }
        if (lane == 0) {
          const float s = 0.125f;  // 1/sqrt(64)
          d00 *= s; d01 *= s; d10 *= s; d11 *= s;
          float m0 = fmaxf(d00, d01), m1 = fmaxf(d10, d11);
          float e00 = expf(d00 - m0), e01 = expf(d01 - m0);
          float e10 = expf(d10 - m1), e11 = expf(d11 - m1);
          float i0 = 1.f / (e00 + e01), i1 = 1.f / (e10 + e11);
          Cf[pair * 8 + h * 2 + 0] = 0.5f * (e00 * i0 + e10 * i1);
          Cf[pair * 8 + h * 2 + 1] = 0.5f * (e01 * i0 + e11 * i1);
        }
      }
    }
  }
  __syncthreads();

  // V GEMM; combine pairs in epilogue -> Ms (reuses Qs region)
  gemmT<32, 16>(fetchT, Wv, Adup, Wbuf, acc, rbase, lane);
  {
    float* Ms = Qs;
    float4 blo = *(const float4*)(bv + 4 * lane);
    float4 bhi = *(const float4*)(bv + 4 * lane + 128);
    int hlo = lane >> 4;        // head of cols 4*lane..4*lane+3
    int hhi = 2 + (lane >> 4);  // head of cols +128
    #pragma unroll
    for (int q = 0; q < 2; q++) {
      int pair = rg * 2 + q;
      float c0l = Cf[pair * 8 + hlo * 2 + 0], c1l = Cf[pair * 8 + hlo * 2 + 1];
      float c0h = Cf[pair * 8 + hhi * 2 + 0], c1h = Cf[pair * 8 + hhi * 2 + 1];
      float2 a00 = funpack(acc[2 * q][0]),     a01 = funpack(acc[2 * q][1]);
      float2 a02 = funpack(acc[2 * q][2]),     a03 = funpack(acc[2 * q][3]);
      float2 a10 = funpack(acc[2 * q + 1][0]), a11 = funpack(acc[2 * q + 1][1]);
      float2 a12 = funpack(acc[2 * q + 1][2]), a13 = funpack(acc[2 * q + 1][3]);
      // coefs sum to 1 -> bias passes straight through
      float4 lo = make_float4(c0l * a00.x + c1l * a10.x + blo.x,
                              c0l * a00.y + c1l * a10.y + blo.y,
                              c0l * a01.x + c1l * a11.x + blo.z,
                              c0l * a01.y + c1l * a11.y + blo.w);
      float4 hi = make_float4(c0h * a02.x + c1h * a12.x + bhi.x,
                              c0h * a02.y + c1h * a12.y + bhi.y,
                              c0h * a03.x + c1h * a13.x + bhi.z,
                              c0h * a03.y + c1h * a13.y + bhi.w);
      *(float4*)(Ms + pair * 256 + 4 * lane) = lo;
      *(float4*)(Ms + pair * 256 + 4 * lane + 128) = hi;
    }
  }
  __syncthreads();

  // O = Ms @ Wo + bo; final = Os @ Wfc + bfc  (16 rows, NR=2)
  auto fetchMs = [&](int c, int ar, int aseg) -> float4 {
    return *(const float4*)(Qs + ar * 256 + c * CH + aseg);
  };
  auto fetchOs = [&](int c, int ar, int aseg) -> float4 {
    return *(const float4*)(Ks + ar * 256 + c * CH + aseg);
  };
  int rbase2 = rg * 2;
  ull acc2[2][4];
  gemmT<16, 16>(fetchMs, Wo, Adup, Wbuf, acc2, rbase2, lane);
  epi_smem2<2, 0>(acc2, bo, Ks, rbase2, lane);
  gemmT<16, 16>(fetchOs, Wfc, Adup, Wbuf, acc2, rbase2, lane);
  epi_gmem2<2>(acc2, bfc, out, rows_a, rbase2, lane, avg);
}

// ---------------- fused expert kernel --------------------------------------
#define NB_ATTN  (B_ROWS / 16)          // 8192
#define NB_MLP   (B_ROWS / 64)          // 2048

__global__ void __launch_bounds__(256, 2) k_experts(
    const float* __restrict__ zg, const float* __restrict__ zi,
    const float* __restrict__ cW1, const float* __restrict__ cb1,
    const float* __restrict__ cW2, const float* __restrict__ cb2,
    const float* __restrict__ mW1, const float* __restrict__ mb1,
    const float* __restrict__ mW2, const float* __restrict__ mb2,
    const float* __restrict__ aWq, const float* __restrict__ abq,
    const float* __restrict__ aWk, const float* __restrict__ abk,
    const float* __restrict__ aWv, const float* __restrict__ abv,
    const float* __restrict__ aWo, const float* __restrict__ abo,
    const float* __restrict__ aWfc, const float* __restrict__ abfc,
    const float* __restrict__ wWa, const float* __restrict__ wba,
    const float* __restrict__ wWo, const float* __restrict__ wbo,
    float* __restrict__ out)
{
  int b = blockIdx.x;
  if (b < NB_ATTN) {
    attn_body(b, zg, zi, aWq, abq, aWk, abk, aWv, abv, aWo, abo, aWfc, abfc, out);
  } else if (b < NB_ATTN + NB_MLP) {
    mlp_body<0>(b - NB_ATTN, 0, zg, zi, cW1, cb1, cW2, cb2, out);
  } else if (b < NB_ATTN + 2 * NB_MLP) {
    mlp_body<1>(b - NB_ATTN - NB_MLP, 1, zg, zi, mW1, mb1, mW2, mb2, out);
  } else {
    mlp_body<2>(b - NB_ATTN - 2 * NB_MLP, 3, zg, zi, wWa, wba, wWo, wbo, out);
  }
}

// ---------------- launch ---------------------------------------------------
extern "C" void kernel_launch(void* const* d_in, const int* in_sizes, int n_in,
                              void* d_out, int out_size) {
  (void)in_sizes; (void)n_in;
  const float* zg  = (const float*)d_in[0];
  const float* zi  = (const float*)d_in[1];
  const float* gW  = (const float*)d_in[2];
  const float* gb  = (const float*)d_in[3];
  const float* cW1 = (const float*)d_in[4];
  const float* cb1 = (const float*)d_in[5];
  const float* cW2 = (const float*)d_in[6];
  const float* cb2 = (const float*)d_in[7];
  const float* mW1 = (const float*)d_in[8];
  const float* mb1 = (const float*)d_in[9];
  const float* mW2 = (const float*)d_in[10];
  const float* mb2 = (const float*)d_in[11];
  const float* aWq = (const float*)d_in[12];
  const float* abq = (const float*)d_in[13];
  const float* aWk = (const float*)d_in[14];
  const float* abk = (const float*)d_in[15];
  const float* aWv = (const float*)d_in[16];
  const float* abv = (const float*)d_in[17];
  const float* aWo = (const float*)d_in[18];
  const float* abo = (const float*)d_in[19];
  const float* aWfc = (const float*)d_in[20];
  const float* abfc = (const float*)d_in[21];
  const float* wWa = (const float*)d_in[22];
  const float* wba = (const float*)d_in[23];
  const float* wWo = (const float*)d_in[24];
  const float* wbo = (const float*)d_in[25];
  float* out = (float*)d_out;

  const int SM_EXP = (16384 + 8192 + 2048) * 4;   // 106496 B

  cudaFuncSetAttribute(k_experts, cudaFuncAttributeMaxDynamicSharedMemorySize, SM_EXP);

  k_reset<<<1, 32>>>();
  k_gate<<<B_ROWS / 8, 256>>>(zg, zi, gW, gb);
  k_finalize<<<1, 32>>>(out, out_size);
  k_experts<<<NB_ATTN + 3 * NB_MLP, 256, SM_EXP>>>(
      zg, zi, cW1, cb1, cW2, cb2, mW1, mb1, mW2, mb2,
      aWq, abq, aWk, abk, aWv, abv, aWo, abo, aWfc, abfc,
      wWa, wba, wWo, wbo, out);
}

// round 10
// speedup vs baseline: 2.2811x; 1.1508x over previous
#include <cuda_runtime.h>
#include <math.h>

#define B_ROWS 131072
#define NEXP   4
#define CH     16      // K-chunk size

typedef unsigned long long ull;

// ---------------- device scratch ------------------------------------------
__device__ int    g_count[NEXP];
__device__ double g_probsum[NEXP];
__device__ float  g_avg[NEXP];
__device__ int    g_bucket[NEXP * B_ROWS];
__device__ float  g_mid[(size_t)B_ROWS * 256];   // attn combined rows (128MB)

// ---------------- f32x2 helpers -------------------------------------------
__device__ __forceinline__ void ffma2(ull& d, ull a, ull b) {
  asm("fma.rn.f32x2 %0, %1, %2, %0;" : "+l"(d) : "l"(a), "l"(b));
}
__device__ __forceinline__ float2 funpack(ull v) {
  float2 f; asm("mov.b64 {%0, %1}, %2;" : "=f"(f.x), "=f"(f.y) : "l"(v)); return f;
}

// ---------------- cp.async helpers ----------------------------------------
__device__ __forceinline__ void cp16(void* sdst, const void* gsrc) {
  unsigned s = (unsigned)__cvta_generic_to_shared(sdst);
  asm volatile("cp.async.cg.shared.global [%0], [%1], 16;\n" :: "r"(s), "l"(gsrc));
}
__device__ __forceinline__ void cp_commit() {
  asm volatile("cp.async.commit_group;\n" ::: "memory");
}
__device__ __forceinline__ void cp_wait1() {
  asm volatile("cp.async.wait_group 1;\n" ::: "memory");
}

// W chunk: CH x 256 floats (16KB). 256 threads, 4 cp16 each.
__device__ __forceinline__ void stage_W(float* Wbuf, const float* Wg, int kc) {
  int t = threadIdx.x;
  const float4* src = (const float4*)(Wg + (size_t)kc * 256);
  #pragma unroll
  for (int i = 0; i < 4; i++)
    cp16(Wbuf + (i * 256 + t) * 4, src + i * 256 + t);
}

// ---------------- packed-FMA chunk ----------------------------------------
// Thread tile: NR rows x 8 cols (4L..4L+3, 4L+128..131). A fetched as
// ulonglong2 broadcast (2 k-steps per LDS.128).
template<int NR>
__device__ __forceinline__ void chunk2(
    const ull* __restrict__ Adup, const float* __restrict__ Wb,
    ull (&acc)[NR][4], int rbase, int lane)
{
  #pragma unroll
  for (int k2 = 0; k2 < CH / 2; k2++) {
    int k = 2 * k2;
    ulonglong2 w0lo = *(const ulonglong2*)(Wb + k * 256 + 4 * lane);
    ulonglong2 w0hi = *(const ulonglong2*)(Wb + k * 256 + 4 * lane + 128);
    ulonglong2 w1lo = *(const ulonglong2*)(Wb + (k + 1) * 256 + 4 * lane);
    ulonglong2 w1hi = *(const ulonglong2*)(Wb + (k + 1) * 256 + 4 * lane + 128);
    #pragma unroll
    for (int r = 0; r < NR; r++) {
      ulonglong2 a2 = *(const ulonglong2*)(Adup + (rbase + r) * CH + k);
      ffma2(acc[r][0], a2.x, w0lo.x);
      ffma2(acc[r][1], a2.x, w0lo.y);
      ffma2(acc[r][2], a2.x, w0hi.x);
      ffma2(acc[r][3], a2.x, w0hi.y);
      ffma2(acc[r][0], a2.y, w1lo.x);
      ffma2(acc[r][1], a2.y, w1lo.y);
      ffma2(acc[r][2], a2.y, w1hi.x);
      ffma2(acc[r][3], a2.y, w1hi.y);
    }
  }
}

// ---------------- generic GEMM core ----------------------------------------
template<int ROWS, int NC, class F>
__device__ __forceinline__ void gemmT(
    F fetch, const float* __restrict__ Wg,
    ull* Adup, float* Wbuf, ull (&acc)[ROWS / 8][4], int rbase, int lane)
{
  constexpr int NR = ROWS / 8;
  #pragma unroll
  for (int r = 0; r < NR; r++)
    #pragma unroll
    for (int c = 0; c < 4; c++) acc[r][c] = 0ULL;
  int t = threadIdx.x;
  int ar = t >> 2, aseg = (t & 3) * 4;
  bool act = (ar < ROWS);
  float4 av = make_float4(0.f, 0.f, 0.f, 0.f);
  if (act) av = fetch(0, ar, aseg);
  stage_W(Wbuf, Wg, 0);             cp_commit();
  stage_W(Wbuf + CH * 256, Wg, CH); cp_commit();
  #pragma unroll 1
  for (int c = 0; c < NC; c++) {
    if (act) {
      float4* d = (float4*)(Adup + ar * CH + aseg);
      d[0] = make_float4(av.x, av.x, av.y, av.y);
      d[1] = make_float4(av.z, av.z, av.w, av.w);
      if (c + 1 < NC) av = fetch(c + 1, ar, aseg);
    }
    cp_wait1(); __syncthreads();
    chunk2<NR>(Adup, Wbuf + (c & 1) * (CH * 256), acc, rbase, lane);
    __syncthreads();
    if (c + 2 < NC) stage_W(Wbuf + (c & 1) * (CH * 256), Wg, (c + 2) * CH);
    cp_commit();
  }
}

// ---------------- epilogues ------------------------------------------------
template<int NR, int ACT>
__device__ __forceinline__ void epi_smem2(
    ull (&acc)[NR][4], const float* __restrict__ bias,
    float* Cs, int rbase, int lane)
{
  float4 blo = *(const float4*)(bias + 4 * lane);
  float4 bhi = *(const float4*)(bias + 4 * lane + 128);
  #pragma unroll
  for (int r = 0; r < NR; r++) {
    float2 v0 = funpack(acc[r][0]), v1 = funpack(acc[r][1]);
    float2 v2 = funpack(acc[r][2]), v3 = funpack(acc[r][3]);
    float4 lo = make_float4(v0.x + blo.x, v0.y + blo.y, v1.x + blo.z, v1.y + blo.w);
    float4 hi = make_float4(v2.x + bhi.x, v2.y + bhi.y, v3.x + bhi.z, v3.y + bhi.w);
    if (ACT == 1) {
      lo.x = fmaxf(lo.x, 0.f); lo.y = fmaxf(lo.y, 0.f); lo.z = fmaxf(lo.z, 0.f); lo.w = fmaxf(lo.w, 0.f);
      hi.x = fmaxf(hi.x, 0.f); hi.y = fmaxf(hi.y, 0.f); hi.z = fmaxf(hi.z, 0.f); hi.w = fmaxf(hi.w, 0.f);
    }
    if (ACT == 2) {
      lo.x = 1.f/(1.f+expf(-lo.x)); lo.y = 1.f/(1.f+expf(-lo.y));
      lo.z = 1.f/(1.f+expf(-lo.z)); lo.w = 1.f/(1.f+expf(-lo.w));
      hi.x = 1.f/(1.f+expf(-hi.x)); hi.y = 1.f/(1.f+expf(-hi.y));
      hi.z = 1.f/(1.f+expf(-hi.z)); hi.w = 1.f/(1.f+expf(-hi.w));
    }
    *(float4*)(Cs + (rbase + r) * 256 + 4 * lane) = lo;
    *(float4*)(Cs + (rbase + r) * 256 + 4 * lane + 128) = hi;
  }
  __syncthreads();
}

template<int NR>
__device__ __forceinline__ void epi_gmem2(
    ull (&acc)[NR][4], const float* __restrict__ bias,
    float* __restrict__ out, const int* rows, int rbase, int lane, float avg)
{
  float4 blo = *(const float4*)(bias + 4 * lane);
  float4 bhi = *(const float4*)(bias + 4 * lane + 128);
  #pragma unroll
  for (int r = 0; r < NR; r++) {
    int row = rows[rbase + r];
    if (row < 0) continue;
    float2 v0 = funpack(acc[r][0]), v1 = funpack(acc[r][1]);
    float2 v2 = funpack(acc[r][2]), v3 = funpack(acc[r][3]);
    float4 lo = make_float4((v0.x + blo.x) * avg, (v0.y + blo.y) * avg,
                            (v1.x + blo.z) * avg, (v1.y + blo.w) * avg);
    float4 hi = make_float4((v2.x + bhi.x) * avg, (v2.y + bhi.y) * avg,
                            (v3.x + bhi.z) * avg, (v3.y + bhi.w) * avg);
    *(float4*)(out + (size_t)row * 256 + 4 * lane) = lo;
    *(float4*)(out + (size_t)row * 256 + 4 * lane + 128) = hi;
  }
}

// ---------------- reset / gate / finalize ----------------------------------
__global__ void k_reset() {
  int t = threadIdx.x;
  if (t < NEXP) { g_count[t] = 0; g_probsum[t] = 0.0; }
}

__global__ void __launch_bounds__(256) k_gate(
    const float* __restrict__ zg, const float* __restrict__ zi,
    const float* __restrict__ gW, const float* __restrict__ gb)
{
  __shared__ float  sW[2048];
  __shared__ int    s_cnt[NEXP];
  __shared__ double s_psum[NEXP];
  __shared__ int    s_base[NEXP];
  int tid = threadIdx.x;
  for (int i = tid; i < 2048; i += 256) sW[i] = gW[i];
  if (tid < NEXP) { s_cnt[tid] = 0; s_psum[tid] = 0.0; }
  __syncthreads();

  int lane = tid & 31, warp = tid >> 5;
  int row  = blockIdx.x * 8 + warp;
  const float4* zg4 = (const float4*)(zg + (size_t)row * 256);
  const float4* zi4 = (const float4*)(zi + (size_t)row * 256);
  float a0 = 0.f, a1 = 0.f, a2 = 0.f, a3 = 0.f;
  float4 xs[4];
  xs[0] = zg4[lane]; xs[1] = zg4[lane + 32];
  xs[2] = zi4[lane]; xs[3] = zi4[lane + 32];
  int dbase[4] = { 4 * lane, 128 + 4 * lane, 256 + 4 * lane, 384 + 4 * lane };
  #pragma unroll
  for (int q = 0; q < 4; q++) {
    const float* xv = (const float*)&xs[q];
    #pragma unroll
    for (int j = 0; j < 4; j++) {
      float x = xv[j];
      float4 w = *(const float4*)&sW[(dbase[q] + j) * 4];
      a0 += x * w.x; a1 += x * w.y; a2 += x * w.z; a3 += x * w.w;
    }
  }
  #pragma unroll
  for (int off = 16; off; off >>= 1) {
    a0 += __shfl_down_sync(0xffffffffu, a0, off);
    a1 += __shfl_down_sync(0xffffffffu, a1, off);
    a2 += __shfl_down_sync(0xffffffffu, a2, off);
    a3 += __shfl_down_sync(0xffffffffu, a3, off);
  }
  int myE = 0, myslot = 0;
  if (lane == 0) {
    float l0 = a0 + gb[0], l1 = a1 + gb[1], l2 = a2 + gb[2], l3 = a3 + gb[3];
    float m = fmaxf(fmaxf(l0, l1), fmaxf(l2, l3));
    float s = expf(l0 - m) + expf(l1 - m) + expf(l2 - m) + expf(l3 - m);
    int best = 0; float bl = l0;
    if (l1 > bl) { bl = l1; best = 1; }
    if (l2 > bl) { bl = l2; best = 2; }
    if (l3 > bl) { bl = l3; best = 3; }
    float p = expf(bl - m) / s;
    myslot = atomicAdd(&s_cnt[best], 1);
    atomicAdd(&s_psum[best], (double)p);
    myE = best;
  }
  __syncthreads();
  if (tid < NEXP) {
    s_base[tid] = atomicAdd(&g_count[tid], s_cnt[tid]);
    atomicAdd(&g_probsum[tid], s_psum[tid]);
  }
  __syncthreads();
  if (lane == 0) g_bucket[myE * B_ROWS + s_base[myE] + myslot] = row;
}

__global__ void k_finalize(float* out, int out_size) {
  int t = threadIdx.x;
  if (t < NEXP) {
    int c = g_count[t];
    g_avg[t] = (c > 0) ? (float)(g_probsum[t] / (double)c) : 0.f;
  }
  __syncthreads();
  if (t == 0) {
    float aux = 0.f;
    #pragma unroll
    for (int e = 0; e < NEXP; e++) {
      float u = (float)g_count[e] / (float)B_ROWS;
      aux += u * u;
    }
    aux *= (float)NEXP;
    if (out_size > B_ROWS * 256) out[(size_t)B_ROWS * 256] = aux;
  }
}

// ---------------- expert bodies --------------------------------------------
extern __shared__ float sm[];
#define SMF_HS    0
#define SMF_WBUF  16384
#define SMF_ADUP  24576

// generic 2-layer MLP expert (concat / mul / wsum variants)
template<int MODE>   // 0=concat, 1=mul, 2=wsum
__device__ __forceinline__ void mlp_body(
    int bid, int eid,
    const float* __restrict__ zg, const float* __restrict__ zi,
    const float* __restrict__ W1, const float* __restrict__ b1,
    const float* __restrict__ W2, const float* __restrict__ b2,
    float* __restrict__ out)
{
  int cnt = g_count[eid];
  int base = bid * 64;
  if (base >= cnt) return;
  float avg = g_avg[eid];
  float* Hs   = sm + SMF_HS;
  float* Wbuf = sm + SMF_WBUF;
  ull*   Adup = (ull*)(sm + SMF_ADUP);
  __shared__ int rows_m[64];
  __shared__ const float* ptab_m[128];
  int tid = threadIdx.x;
  int lane = tid & 31, rbase = (tid >> 5) * 8;
  if (tid < 64) {
    int i = base + tid;
    int row = (i < cnt) ? g_bucket[eid * B_ROWS + i] : -1;
    rows_m[tid] = row;
    size_t rr = (size_t)(row < 0 ? 0 : row) * 256;
    ptab_m[tid]      = zg + rr;
    ptab_m[64 + tid] = zi + rr;
  }
  __syncthreads();
  auto fetchCat = [&](int c, int ar, int aseg) -> float4 {
    int kc = c * CH;
    return *(const float4*)(ptab_m[((kc >> 8) << 6) + ar] + (kc & 255) + aseg);
  };
  auto fetchMul = [&](int c, int ar, int aseg) -> float4 {
    int kc = c * CH;
    float4 g = *(const float4*)(ptab_m[ar] + kc + aseg);
    float4 z = *(const float4*)(ptab_m[64 + ar] + kc + aseg);
    return make_float4(g.x * z.x, g.y * z.y, g.z * z.z, g.w * z.w);
  };
  auto fetchH = [&](int c, int ar, int aseg) -> float4 {
    return *(const float4*)(Hs + ar * 256 + c * CH + aseg);
  };
  auto fetchHW = [&](int c, int ar, int aseg) -> float4 {
    int kc = c * CH;
    float4 a = *(const float4*)(Hs + ar * 256 + kc + aseg);
    float4 g = *(const float4*)(ptab_m[ar] + kc + aseg);
    float4 z = *(const float4*)(ptab_m[64 + ar] + kc + aseg);
    return make_float4(a.x * g.x + (1.f - a.x) * z.x,
                       a.y * g.y + (1.f - a.y) * z.y,
                       a.z * g.z + (1.f - a.z) * z.z,
                       a.w * g.w + (1.f - a.w) * z.w);
  };
  ull acc[8][4];
  if (MODE == 0) {
    gemmT<64, 32>(fetchCat, W1, Adup, Wbuf, acc, rbase, lane);
    epi_smem2<8, 1>(acc, b1, Hs, rbase, lane);
    gemmT<64, 16>(fetchH, W2, Adup, Wbuf, acc, rbase, lane);
  } else if (MODE == 1) {
    gemmT<64, 16>(fetchMul, W1, Adup, Wbuf, acc, rbase, lane);
    epi_smem2<8, 1>(acc, b1, Hs, rbase, lane);
    gemmT<64, 16>(fetchH, W2, Adup, Wbuf, acc, rbase, lane);
  } else {
    gemmT<64, 32>(fetchCat, W1, Adup, Wbuf, acc, rbase, lane);
    epi_smem2<8, 2>(acc, b1, Hs, rbase, lane);   // alpha = sigmoid
    gemmT<64, 16>(fetchHW, W2, Adup, Wbuf, acc, rbase, lane);
  }
  epi_gmem2<8>(acc, b2, out, rows_m, rbase, lane, avg);
}

// attn pass A: 32 pairs (64 token rows) per block, all GEMMs ROWS=64/NR=8.
// Q -> smem; K epilogue computes head dots vs Q; softmax coefs;
// V epilogue combines pairs -> g_mid.
__device__ __forceinline__ void attn_bodyA(
    int bid,
    const float* __restrict__ zg, const float* __restrict__ zi,
    const float* __restrict__ Wq, const float* __restrict__ bq,
    const float* __restrict__ Wk, const float* __restrict__ bk,
    const float* __restrict__ Wv, const float* __restrict__ bv)
{
  int cnt = g_count[2];
  int base = bid * 32;                   // pair base
  if (base >= cnt) return;
  float* Qs   = sm + SMF_HS;             // 64 x 256
  float* Wbuf = sm + SMF_WBUF;
  ull*   Adup = (ull*)(sm + SMF_ADUP);
  __shared__ const float* ptab_a[64];
  __shared__ float sc[32][4][2][2];      // [pair][head][t_q][t_k]
  __shared__ float Cf[32 * 8];
  int tid = threadIdx.x;
  int lane = tid & 31, rbase = (tid >> 5) * 8;
  if (tid < 64) {
    int pair = tid >> 1;
    int i = base + pair;
    int row = (i < cnt) ? g_bucket[2 * B_ROWS + i] : 0;
    size_t rr = (size_t)row * 256;
    ptab_a[tid] = ((tid & 1) ? zi : zg) + rr;
  }
  __syncthreads();

  auto fetchT = [&](int c, int ar, int aseg) -> float4 {
    return *(const float4*)(ptab_a[ar] + c * CH + aseg);
  };

  ull acc[8][4];
  // ---- Q ----
  gemmT<64, 16>(fetchT, Wq, Adup, Wbuf, acc, rbase, lane);
  epi_smem2<8, 0>(acc, bq, Qs, rbase, lane);
  // ---- K (epilogue computes scores) ----
  gemmT<64, 16>(fetchT, Wk, Adup, Wbuf, acc, rbase, lane);
  {
    float4 bklo = *(const float4*)(bk + 4 * lane);
    float4 bkhi = *(const float4*)(bk + 4 * lane + 128);
    int g = lane >> 4;
    #pragma unroll
    for (int ri = 0; ri < 8; ri++) {
      int r = rbase + ri;
      int p = r >> 1, tk = r & 1;
      float2 v0 = funpack(acc[ri][0]), v1 = funpack(acc[ri][1]);
      float2 v2 = funpack(acc[ri][2]), v3 = funpack(acc[ri][3]);
      float kl0 = v0.x + bklo.x, kl1 = v0.y + bklo.y;
      float kl2 = v1.x + bklo.z, kl3 = v1.y + bklo.w;
      float kh0 = v2.x + bkhi.x, kh1 = v2.y + bkhi.y;
      float kh2 = v3.x + bkhi.z, kh3 = v3.y + bkhi.w;
      #pragma unroll
      for (int tq = 0; tq < 2; tq++) {
        const float* q = Qs + (2 * p + tq) * 256;
        float4 qlo = *(const float4*)(q + 4 * lane);
        float4 qhi = *(const float4*)(q + 4 * lane + 128);
        float slo = kl0 * qlo.x + kl1 * qlo.y + kl2 * qlo.z + kl3 * qlo.w;
        float shi = kh0 * qhi.x + kh1 * qhi.y + kh2 * qhi.z + kh3 * qhi.w;
        #pragma unroll
        for (int off = 8; off; off >>= 1) {
          slo += __shfl_down_sync(0xffffffffu, slo, off, 16);
          shi += __shfl_down_sync(0xffffffffu, shi, off, 16);
        }
        if ((lane & 15) == 0) {
          sc[p][g][tq][tk]     = slo;   // heads 0/1
          sc[p][2 + g][tq][tk] = shi;   // heads 2/3
        }
      }
    }
  }
  __syncthreads();
  // ---- softmax -> pair coefficients ----
  if (tid < 128) {
    int p = tid >> 2, h = tid & 3;
    const float s = 0.125f;   // 1/sqrt(64)
    float s00 = sc[p][h][0][0] * s, s01 = sc[p][h][0][1] * s;
    float s10 = sc[p][h][1][0] * s, s11 = sc[p][h][1][1] * s;
    float m0 = fmaxf(s00, s01), m1 = fmaxf(s10, s11);
    float e00 = expf(s00 - m0), e01 = expf(s01 - m0);
    float e10 = expf(s10 - m1), e11 = expf(s11 - m1);
    float i0 = 1.f / (e00 + e01), i1 = 1.f / (e10 + e11);
    Cf[p * 8 + h * 2 + 0] = 0.5f * (e00 * i0 + e10 * i1);
    Cf[p * 8 + h * 2 + 1] = 0.5f * (e01 * i0 + e11 * i1);
  }
  __syncthreads();
  // ---- V (epilogue combines pairs -> g_mid) ----
  gemmT<64, 16>(fetchT, Wv, Adup, Wbuf, acc, rbase, lane);
  {
    float4 bvlo = *(const float4*)(bv + 4 * lane);
    float4 bvhi = *(const float4*)(bv + 4 * lane + 128);
    int hlo = lane >> 4, hhi = 2 + (lane >> 4);
    #pragma unroll
    for (int q = 0; q < 4; q++) {
      int p = (rbase >> 1) + q;
      int gp = base + p;
      if (gp >= cnt) continue;
      float c0l = Cf[p * 8 + hlo * 2 + 0], c1l = Cf[p * 8 + hlo * 2 + 1];
      float c0h = Cf[p * 8 + hhi * 2 + 0], c1h = Cf[p * 8 + hhi * 2 + 1];
      float2 a00 = funpack(acc[2 * q][0]),     a01 = funpack(acc[2 * q][1]);
      float2 a02 = funpack(acc[2 * q][2]),     a03 = funpack(acc[2 * q][3]);
      float2 a10 = funpack(acc[2 * q + 1][0]), a11 = funpack(acc[2 * q + 1][1]);
      float2 a12 = funpack(acc[2 * q + 1][2]), a13 = funpack(acc[2 * q + 1][3]);
      // coefs sum to 1 -> bias passes straight through
      float4 lo = make_float4(c0l * a00.x + c1l * a10.x + bvlo.x,
                              c0l * a00.y + c1l * a10.y + bvlo.y,
                              c0l * a01.x + c1l * a11.x + bvlo.z,
                              c0l * a01.y + c1l * a11.y + bvlo.w);
      float4 hi = make_float4(c0h * a02.x + c1h * a12.x + bvhi.x,
                              c0h * a02.y + c1h * a12.y + bvhi.y,
                              c0h * a03.x + c1h * a13.x + bvhi.z,
                              c0h * a03.y + c1h * a13.y + bvhi.w);
      *(float4*)(g_mid + (size_t)gp * 256 + 4 * lane) = lo;
      *(float4*)(g_mid + (size_t)gp * 256 + 4 * lane + 128) = hi;
    }
  }
}

// ---------------- fused expert kernel --------------------------------------
#define NB_ATTN  (B_ROWS / 32)          // 4096
#define NB_MLP   (B_ROWS / 64)          // 2048

__global__ void __launch_bounds__(256, 2) k_experts(
    const float* __restrict__ zg, const float* __restrict__ zi,
    const float* __restrict__ cW1, const float* __restrict__ cb1,
    const float* __restrict__ cW2, const float* __restrict__ cb2,
    const float* __restrict__ mW1, const float* __restrict__ mb1,
    const float* __restrict__ mW2, const float* __restrict__ mb2,
    const float* __restrict__ aWq, const float* __restrict__ abq,
    const float* __restrict__ aWk, const float* __restrict__ abk,
    const float* __restrict__ aWv, const float* __restrict__ abv,
    const float* __restrict__ wWa, const float* __restrict__ wba,
    const float* __restrict__ wWo, const float* __restrict__ wbo,
    float* __restrict__ out)
{
  int b = blockIdx.x;
  if (b < NB_ATTN) {
    attn_bodyA(b, zg, zi, aWq, abq, aWk, abk, aWv, abv);
  } else if (b < NB_ATTN + NB_MLP) {
    mlp_body<0>(b - NB_ATTN, 0, zg, zi, cW1, cb1, cW2, cb2, out);
  } else if (b < NB_ATTN + 2 * NB_MLP) {
    mlp_body<1>(b - NB_ATTN - NB_MLP, 1, zg, zi, mW1, mb1, mW2, mb2, out);
  } else {
    mlp_body<2>(b - NB_ATTN - 2 * NB_MLP, 3, zg, zi, wWa, wba, wWo, wbo, out);
  }
}

// ---------------- attn pass B: Wo -> Wfc on combined rows -------------------
__global__ void __launch_bounds__(256, 2) k_attn2(
    const float* __restrict__ Wo, const float* __restrict__ bo,
    const float* __restrict__ Wfc, const float* __restrict__ bfc,
    float* __restrict__ out)
{
  int cnt = g_count[2];
  int base = blockIdx.x * 64;
  if (base >= cnt) return;
  float avg = g_avg[2];
  float* Hs   = sm + SMF_HS;
  float* Wbuf = sm + SMF_WBUF;
  ull*   Adup = (ull*)(sm + SMF_ADUP);
  __shared__ int rows_b[64];
  int tid = threadIdx.x;
  int lane = tid & 31, rbase = (tid >> 5) * 8;
  if (tid < 64) {
    int i = base + tid;
    rows_b[tid] = (i < cnt) ? g_bucket[2 * B_ROWS + i] : -1;
  }
  __syncthreads();
  auto fetchMid = [&](int c, int ar, int aseg) -> float4 {
    return *(const float4*)(g_mid + (size_t)(base + ar) * 256 + c * CH + aseg);
  };
  auto fetchH = [&](int c, int ar, int aseg) -> float4 {
    return *(const float4*)(Hs + ar * 256 + c * CH + aseg);
  };
  ull acc[8][4];
  gemmT<64, 16>(fetchMid, Wo, Adup, Wbuf, acc, rbase, lane);
  epi_smem2<8, 0>(acc, bo, Hs, rbase, lane);
  gemmT<64, 16>(fetchH, Wfc, Adup, Wbuf, acc, rbase, lane);
  epi_gmem2<8>(acc, bfc, out, rows_b, rbase, lane, avg);
}

// ---------------- launch ---------------------------------------------------
extern "C" void kernel_launch(void* const* d_in, const int* in_sizes, int n_in,
                              void* d_out, int out_size) {
  (void)in_sizes; (void)n_in;
  const float* zg  = (const float*)d_in[0];
  const float* zi  = (const float*)d_in[1];
  const float* gW  = (const float*)d_in[2];
  const float* gb  = (const float*)d_in[3];
  const float* cW1 = (const float*)d_in[4];
  const float* cb1 = (const float*)d_in[5];
  const float* cW2 = (const float*)d_in[6];
  const float* cb2 = (const float*)d_in[7];
  const float* mW1 = (const float*)d_in[8];
  const float* mb1 = (const float*)d_in[9];
  const float* mW2 = (const float*)d_in[10];
  const float* mb2 = (const float*)d_in[11];
  const float* aWq = (const float*)d_in[12];
  const float* abq = (const float*)d_in[13];
  const float* aWk = (const float*)d_in[14];
  const float* abk = (const float*)d_in[15];
  const float* aWv = (const float*)d_in[16];
  const float* abv = (const float*)d_in[17];
  const float* aWo = (const float*)d_in[18];
  const float* abo = (const float*)d_in[19];
  const float* aWfc = (const float*)d_in[20];
  const float* abfc = (const float*)d_in[21];
  const float* wWa = (const float*)d_in[22];
  const float* wba = (const float*)d_in[23];
  const float* wWo = (const float*)d_in[24];
  const float* wbo = (const float*)d_in[25];
  float* out = (float*)d_out;

  const int SM_EXP = (16384 + 8192 + 2048) * 4;   // 106496 B

  cudaFuncSetAttribute(k_experts, cudaFuncAttributeMaxDynamicSharedMemorySize, SM_EXP);
  cudaFuncSetAttribute(k_attn2,   cudaFuncAttributeMaxDynamicSharedMemorySize, SM_EXP);

  k_reset<<<1, 32>>>();
  k_gate<<<B_ROWS / 8, 256>>>(zg, zi, gW, gb);
  k_finalize<<<1, 32>>>(out, out_size);
  k_experts<<<NB_ATTN + 3 * NB_MLP, 256, SM_EXP>>>(
      zg, zi, cW1, cb1, cW2, cb2, mW1, mb1, mW2, mb2,
      aWq, abq, aWk, abk, aWv, abv,
      wWa, wba, wWo, wbo, out);
  k_attn2<<<B_ROWS / 64, 256, SM_EXP>>>(aWo, abo, aWfc, abfc, out);
}